// round 9
// baseline (speedup 1.0000x reference)
#include <cuda_runtime.h>
#include <cuda_bf16.h>
#include <cstdint>
#include <cstddef>

#define S 2048
#define D 512
#define NB 4
#define EPSI 0.01f
#define SWZ(x) ((x) ^ (((x) >> 3) & 0x70))
#define SMEMB (98304 + 2048 + 512)

// ---------------- device scratch ----------------
__device__ __align__(128) __nv_bfloat16  g_Ah [(size_t)NB * S * S];
__device__ __align__(128) __nv_bfloat16  g_Wh [(size_t)NB * S * S];
__device__ __align__(128) __nv_bfloat16  g_Wl [(size_t)NB * S * S];
__device__ __align__(128) __nv_bfloat16  g_Mh [(size_t)NB * S * D];
__device__ __align__(128) __nv_bfloat16  g_Vh [(size_t)NB * S * D];
__device__ __align__(128) __nv_bfloat16  g_Vth[(size_t)NB * D * S];
__device__ __align__(128) __nv_bfloat16  g_Vtl[(size_t)NB * D * S];
__device__ __align__(128) float          g_F  [(size_t)NB * S * D];
__device__ __align__(128) float          g_rp [(size_t)NB * 16 * S];
__device__ __align__(128) float          g_mp [(size_t)NB * 4 * S];
__device__ float g_v2[NB * S];

// ---------------- PTX helpers (compute_103-safe only) ----------------
__device__ __forceinline__ uint32_t smem_u32(const void* p) {
    uint32_t a;
    asm("{ .reg .u64 t; cvta.to.shared.u64 t, %1; cvt.u32.u64 %0, t; }" : "=r"(a) : "l"(p));
    return a;
}
__device__ __forceinline__ void cpasync16(uint32_t smem, const void* g) {
    asm volatile("cp.async.cg.shared.global [%0], [%1], 16;" :: "r"(smem), "l"(g));
}
__device__ __forceinline__ void cp_commit() {
    asm volatile("cp.async.commit_group;" ::: "memory");
}
template <int N>
__device__ __forceinline__ void cp_wait() {
    asm volatile("cp.async.wait_group %0;" :: "n"(N) : "memory");
}
__device__ __forceinline__ void ldsm4(uint32_t* r, uint32_t addr) {
    asm volatile("ldmatrix.sync.aligned.m8n8.x4.shared.b16 {%0,%1,%2,%3}, [%4];"
                 : "=r"(r[0]), "=r"(r[1]), "=r"(r[2]), "=r"(r[3]) : "r"(addr));
}
__device__ __forceinline__ void mma_bf16(float* c, const uint32_t* a, uint32_t b0, uint32_t b1) {
    asm volatile("mma.sync.aligned.m16n8k16.row.col.f32.bf16.bf16.f32 "
                 "{%0,%1,%2,%3}, {%4,%5,%6,%7}, {%8,%9}, {%0,%1,%2,%3};"
                 : "+f"(c[0]), "+f"(c[1]), "+f"(c[2]), "+f"(c[3])
                 : "r"(a[0]), "r"(a[1]), "r"(a[2]), "r"(a[3]), "r"(b0), "r"(b1));
}
__device__ __forceinline__ unsigned pkb(__nv_bfloat16 a, __nv_bfloat16 b) {
    unsigned short ua = *(unsigned short*)&a, ub = *(unsigned short*)&b;
    return (unsigned)ua | ((unsigned)ub << 16);
}

// ---------------- small kernels ----------------
__global__ void rownorm_kernel(const float* __restrict__ X, float* __restrict__ out,
                               int cols, int nrows) {
    int warp = (blockIdx.x * blockDim.x + threadIdx.x) >> 5;
    int lane = threadIdx.x & 31;
    if (warp >= nrows) return;
    const float* row = X + (size_t)warp * cols;
    float s = 0.f;
    for (int c = lane * 4; c < cols; c += 128) {
        float4 v = *(const float4*)(row + c);
        s += v.x * v.x + v.y * v.y + v.z * v.z + v.w * v.w;
    }
    #pragma unroll
    for (int off = 16; off >= 1; off >>= 1) s += __shfl_xor_sync(0xffffffffu, s, off);
    if (lane == 0) out[warp] = s;
}

__global__ void convert_hi_kernel(const float* __restrict__ X,
                                  __nv_bfloat16* __restrict__ H, size_t n) {
    size_t i = ((size_t)blockIdx.x * blockDim.x + threadIdx.x) * 4;
    if (i >= n) return;
    float4 v = *(const float4*)(X + i);
    *(uint2*)(H + i) = make_uint2(pkb(__float2bfloat16(v.x), __float2bfloat16(v.y)),
                                  pkb(__float2bfloat16(v.z), __float2bfloat16(v.w)));
}

__global__ void transpose_hilo_kernel(const float* __restrict__ V,
                                      __nv_bfloat16* __restrict__ Th,
                                      __nv_bfloat16* __restrict__ Tl) {
    __shared__ float tile[32][33];
    int b = blockIdx.z, d0 = blockIdx.x * 32, j0 = blockIdx.y * 32;
    int tx = threadIdx.x, ty = threadIdx.y;
    #pragma unroll
    for (int r = 0; r < 32; r += 8)
        tile[ty + r][tx] = V[((size_t)b * S + j0 + ty + r) * D + d0 + tx];
    __syncthreads();
    #pragma unroll
    for (int r = 0; r < 32; r += 8) {
        float x = tile[tx][ty + r];
        __nv_bfloat16 h = __float2bfloat16(x);
        size_t o = ((size_t)b * D + d0 + ty + r) * S + j0 + tx;
        Th[o] = h;
        Tl[o] = __float2bfloat16(x - __bfloat162float(h));
    }
}

// ---------------- HMMA GEMM: C[128,128] = sum_k A[128,k]*B[128,k]^T ----------------
// NPROD=1: BK=64, rows 64 bf16 hi-only; product ah*bh.
// NPROD=2: BK=32, rows [hi 32 | lo 32]; products ah*bh + al*bh (A exact, B hi).
// smem: 3 stages x (A 16KB | B 16KB) = 96KB; red @96K (2KB); rowv @98K+2048 (512B).
// EPI 0: Mh + m2 partials (sc=1)                      [GEMM0]
// EPI 1: weights -> Wh (+Wl if WLO) + L1 partials; m2 from fused prologue [GEMM1]
// EPI 2: Mh + m2 partials, sc=ri (fused prologue)     [GEMM2 mid]
// EPI 3: fp32 store (no scale)                        [F1 = (Wh+Wl)@Vh, NPROD=2]
// EPI 4: (srcF + acc) * ri -> fp32 out                [F2 = Wh@Vl, NPROD=1]
template <int NDIM, int KDIM, int EPI, int NPROD, bool WLO>
__global__ void __launch_bounds__(256, 2)
tc_gemm(const __nv_bfloat16* __restrict__ Ah, const __nv_bfloat16* __restrict__ Al,
        const __nv_bfloat16* __restrict__ Bh,
        float* __restrict__ dstF, __nv_bfloat16* __restrict__ dstH,
        __nv_bfloat16* __restrict__ dstL, const float* __restrict__ Ain) {
    constexpr int BKL = (NPROD == 1) ? 64 : 32;
    constexpr int SST = BKL / 16;
    extern __shared__ char dsm[];
    const uint32_t sb = smem_u32(dsm);
    float* red  = (float*)(dsm + 98304);          // [128][4]
    float* rowv = (float*)(dsm + 98304 + 2048);   // [128]: m2 (EPI1) or ri (EPI2/4)

    const int b = blockIdx.z;
    const int mBase = blockIdx.y * 128;
    const int nBase = blockIdx.x * 128;
    const int tid = threadIdx.x;
    const int lane = tid & 31, wid = tid >> 5;
    const int wm = wid & 1, wn = wid >> 1;         // warp tile: M64 x N32

    const int grow_ld = tid >> 1;
    const int hsel = tid & 1;
    const __nv_bfloat16* pAh = Ah + (size_t)b * S * KDIM + (size_t)(mBase + grow_ld) * KDIM;
    const __nv_bfloat16* pAl = (NPROD == 2) ? Al + (size_t)b * S * KDIM + (size_t)(mBase + grow_ld) * KDIM : nullptr;
    const __nv_bfloat16* pBh = Bh + (size_t)b * NDIM * KDIM + (size_t)(nBase + grow_ld) * KDIM;

    const uint32_t rowb = (uint32_t)grow_ld * 128;
    const int nT = KDIM / BKL;

    auto load_chunk = [&](int t, int stage) {
        if (t < nT) {
            const int kb = t * BKL;
            const uint32_t ab = sb + stage * 16384;
            const uint32_t bb = sb + 49152 + stage * 16384;
            if (NPROD == 2) {
                #pragma unroll
                for (int j = 0; j < 2; ++j) {
                    const int seg = hsel * 2 + j;
                    cpasync16(ab + SWZ(rowb + seg * 16),      pAh + kb + seg * 8);
                    cpasync16(ab + SWZ(rowb + 64 + seg * 16), pAl + kb + seg * 8);
                    cpasync16(bb + SWZ(rowb + seg * 16),      pBh + kb + seg * 8);
                }
            } else {
                #pragma unroll
                for (int j = 0; j < 4; ++j) {
                    const int seg = hsel * 4 + j;
                    cpasync16(ab + SWZ(rowb + seg * 16), pAh + kb + seg * 8);
                    cpasync16(bb + SWZ(rowb + seg * 16), pBh + kb + seg * 8);
                }
            }
        }
        cp_commit();
    };

    float acc[4][4][4];
    #pragma unroll
    for (int i = 0; i < 4; ++i)
        #pragma unroll
        for (int j = 0; j < 4; ++j)
            #pragma unroll
            for (int e = 0; e < 4; ++e) acc[i][j][e] = 0.f;

    load_chunk(0, 0);
    load_chunk(1, 1);

    // ---- fused row-stat prologue (overlaps stage-0/1 loads) ----
    if (EPI == 1 && tid < 128) {
        float s = 0.f;
        #pragma unroll
        for (int t = 0; t < 4; ++t) s += g_mp[((size_t)(b * 4 + t)) * S + mBase + tid];
        rowv[tid] = s;
    }
    if ((EPI == 2 || EPI == 4) && tid < 128) {
        float s = 0.f;
        #pragma unroll
        for (int t = 0; t < 16; ++t) s += g_rp[((size_t)(b * 16 + t)) * S + mBase + tid];
        rowv[tid] = 1.0f / fmaxf(s, 1e-12f);
    }

    const int lrow = lane & 15, cseg = lane >> 4;

    int buf = 0, sld = 2;
    for (int t = 0; t < nT; ++t) {
        cp_wait<1>();
        __syncthreads();
        load_chunk(t + 2, sld);

        const uint32_t ab = sb + buf * 16384;
        const uint32_t bb = sb + 49152 + buf * 16384;

        #pragma unroll
        for (int s = 0; s < SST; ++s) {
            const uint32_t kcol = (uint32_t)(s * 2 + cseg) * 16;
            uint32_t bfh[2][4];
            #pragma unroll
            for (int g = 0; g < 2; ++g) {
                const uint32_t br = (uint32_t)(wn * 32 + g * 16 + lrow) * 128;
                ldsm4(bfh[g], bb + SWZ(br + kcol));
            }
            uint32_t afh[4][4], afl[4][4];
            #pragma unroll
            for (int mf = 0; mf < 4; ++mf) {
                const uint32_t arr = (uint32_t)(wm * 64 + mf * 16 + lrow) * 128;
                ldsm4(afh[mf], ab + SWZ(arr + kcol));
                if (NPROD == 2) ldsm4(afl[mf], ab + SWZ(arr + 64 + kcol));
            }
            #pragma unroll
            for (int mf = 0; mf < 4; ++mf)
                #pragma unroll
                for (int nf = 0; nf < 4; ++nf) {
                    const int g = nf >> 1, h = nf & 1;
                    mma_bf16(acc[mf][nf], afh[mf], bfh[g][h], bfh[g][h + 2]);
                    if (NPROD == 2)
                        mma_bf16(acc[mf][nf], afl[mf], bfh[g][h], bfh[g][h + 2]);
                }
        }
        buf = (buf == 2) ? 0 : buf + 1;
        sld = (sld == 2) ? 0 : sld + 1;
    }

    // ---------------- epilogue ----------------
    const int q = lane >> 2, tq = lane & 3;

    if (EPI == 1) {
        float v2c[4][2];
        #pragma unroll
        for (int nf = 0; nf < 4; ++nf) {
            float2 v2v = *(const float2*)(g_v2 + b * S + nBase + wn * 32 + nf * 8 + tq * 2);
            v2c[nf][0] = v2v.x; v2c[nf][1] = v2v.y;
        }
        #pragma unroll
        for (int mf = 0; mf < 4; ++mf) {
            #pragma unroll
            for (int r2 = 0; r2 < 2; ++r2) {
                const int lr = wm * 64 + mf * 16 + q + r2 * 8;
                const int gr = mBase + lr;
                const float m2v = rowv[lr];
                const float* arow = Ain + ((size_t)b * S + gr) * S + nBase + wn * 32;
                __nv_bfloat16* whp = dstH + ((size_t)b * S + gr) * S + nBase + wn * 32;
                __nv_bfloat16* wlp = WLO ? dstL + ((size_t)b * S + gr) * S + nBase + wn * 32 : nullptr;
                float rs = 0.f;
                #pragma unroll
                for (int nf = 0; nf < 4; ++nf) {
                    float2 a2 = *(const float2*)(arow + nf * 8 + tq * 2);
                    float d2 = fmaxf(m2v + v2c[nf][0] - 2.f * acc[mf][nf][r2 * 2], 0.f);
                    float w0 = __fdividef(a2.x, sqrtf(d2) + EPSI);
                    d2 = fmaxf(m2v + v2c[nf][1] - 2.f * acc[mf][nf][r2 * 2 + 1], 0.f);
                    float w1 = __fdividef(a2.y, sqrtf(d2) + EPSI);
                    rs += fabsf(w0) + fabsf(w1);
                    __nv_bfloat16 h0 = __float2bfloat16(w0), h1 = __float2bfloat16(w1);
                    *(unsigned*)(whp + nf * 8 + tq * 2) = pkb(h0, h1);
                    if (WLO)
                        *(unsigned*)(wlp + nf * 8 + tq * 2) =
                            pkb(__float2bfloat16(w0 - __bfloat162float(h0)),
                                __float2bfloat16(w1 - __bfloat162float(h1)));
                }
                rs += __shfl_xor_sync(0xffffffffu, rs, 1);
                rs += __shfl_xor_sync(0xffffffffu, rs, 2);
                if (tq == 0) red[lr * 4 + wn] = rs;
            }
        }
        __syncthreads();
        if (tid < 128) {
            float s = red[tid * 4] + red[tid * 4 + 1] + red[tid * 4 + 2] + red[tid * 4 + 3];
            g_rp[((size_t)(b * 16 + blockIdx.x)) * S + mBase + tid] = s;
        }
    } else if (EPI == 3) {
        #pragma unroll
        for (int mf = 0; mf < 4; ++mf) {
            #pragma unroll
            for (int r2 = 0; r2 < 2; ++r2) {
                const int gr = mBase + wm * 64 + mf * 16 + q + r2 * 8;
                float* fo = dstF + ((size_t)b * S + gr) * NDIM + nBase + wn * 32;
                #pragma unroll
                for (int nf = 0; nf < 4; ++nf)
                    *(float2*)(fo + nf * 8 + tq * 2) =
                        make_float2(acc[mf][nf][r2 * 2], acc[mf][nf][r2 * 2 + 1]);
            }
        }
    } else if (EPI == 4) {
        #pragma unroll
        for (int mf = 0; mf < 4; ++mf) {
            #pragma unroll
            for (int r2 = 0; r2 < 2; ++r2) {
                const int lr = wm * 64 + mf * 16 + q + r2 * 8;
                const int gr = mBase + lr;
                const float sc = rowv[lr];
                const float* fi = Ain + ((size_t)b * S + gr) * NDIM + nBase + wn * 32;
                float* fo = dstF + ((size_t)b * S + gr) * NDIM + nBase + wn * 32;
                #pragma unroll
                for (int nf = 0; nf < 4; ++nf) {
                    float2 p = *(const float2*)(fi + nf * 8 + tq * 2);
                    *(float2*)(fo + nf * 8 + tq * 2) =
                        make_float2((p.x + acc[mf][nf][r2 * 2]) * sc,
                                    (p.y + acc[mf][nf][r2 * 2 + 1]) * sc);
                }
            }
        }
    } else {
        // EPI 0 / 2: bf16 Mh store + m2 partials
        #pragma unroll
        for (int mf = 0; mf < 4; ++mf) {
            #pragma unroll
            for (int r2 = 0; r2 < 2; ++r2) {
                const int lr = wm * 64 + mf * 16 + q + r2 * 8;
                const int gr = mBase + lr;
                const float sc = (EPI == 2) ? rowv[lr] : 1.f;
                __nv_bfloat16* hp = dstH + ((size_t)b * S + gr) * NDIM + nBase + wn * 32;
                float rs = 0.f;
                #pragma unroll
                for (int nf = 0; nf < 4; ++nf) {
                    float o0 = acc[mf][nf][r2 * 2] * sc;
                    float o1 = acc[mf][nf][r2 * 2 + 1] * sc;
                    rs += o0 * o0 + o1 * o1;
                    *(unsigned*)(hp + nf * 8 + tq * 2) =
                        pkb(__float2bfloat16(o0), __float2bfloat16(o1));
                }
                rs += __shfl_xor_sync(0xffffffffu, rs, 1);
                rs += __shfl_xor_sync(0xffffffffu, rs, 2);
                if (tq == 0) red[lr * 4 + wn] = rs;
            }
        }
        __syncthreads();
        if (tid < 128) {
            float s = red[tid * 4] + red[tid * 4 + 1] + red[tid * 4 + 2] + red[tid * 4 + 3];
            g_mp[((size_t)(b * 4 + blockIdx.x)) * S + mBase + tid] = s;
        }
    }
}

// ---------------- launch ----------------
extern "C" void kernel_launch(void* const* d_in, const int* in_sizes, int n_in,
                              void* d_out, int out_size) {
    const float* A = (const float*)d_in[0];
    const float* V = (const float*)d_in[1];
    float* out = (float*)d_out;

    void* p;
    cudaGetSymbolAddress(&p, g_Ah);  __nv_bfloat16* Ah = (__nv_bfloat16*)p;
    cudaGetSymbolAddress(&p, g_Wh);  __nv_bfloat16* Wh = (__nv_bfloat16*)p;
    cudaGetSymbolAddress(&p, g_Wl);  __nv_bfloat16* Wl = (__nv_bfloat16*)p;
    cudaGetSymbolAddress(&p, g_Mh);  __nv_bfloat16* Mh = (__nv_bfloat16*)p;
    cudaGetSymbolAddress(&p, g_Vh);  __nv_bfloat16* Vh = (__nv_bfloat16*)p;
    cudaGetSymbolAddress(&p, g_Vth); __nv_bfloat16* Vth = (__nv_bfloat16*)p;
    cudaGetSymbolAddress(&p, g_Vtl); __nv_bfloat16* Vtl = (__nv_bfloat16*)p;
    cudaGetSymbolAddress(&p, g_F);   float* F = (float*)p;
    cudaGetSymbolAddress(&p, g_v2);  float* v2 = (float*)p;

    cudaFuncSetAttribute(tc_gemm<D, S, 0, 1, false>, cudaFuncAttributeMaxDynamicSharedMemorySize, SMEMB);
    cudaFuncSetAttribute(tc_gemm<S, D, 1, 1, false>, cudaFuncAttributeMaxDynamicSharedMemorySize, SMEMB);
    cudaFuncSetAttribute(tc_gemm<S, D, 1, 1, true>,  cudaFuncAttributeMaxDynamicSharedMemorySize, SMEMB);
    cudaFuncSetAttribute(tc_gemm<D, S, 2, 1, false>, cudaFuncAttributeMaxDynamicSharedMemorySize, SMEMB);
    cudaFuncSetAttribute(tc_gemm<D, S, 3, 2, false>, cudaFuncAttributeMaxDynamicSharedMemorySize, SMEMB);
    cudaFuncSetAttribute(tc_gemm<D, S, 4, 1, false>, cudaFuncAttributeMaxDynamicSharedMemorySize, SMEMB);

    const int nrows = NB * S;
    const size_t nA = (size_t)NB * S * S;
    const size_t nV = (size_t)NB * S * D;

    convert_hi_kernel<<<(unsigned)((nA / 4 + 255) / 256), 256>>>(A, Ah, nA);
    convert_hi_kernel<<<(unsigned)((nV / 4 + 255) / 256), 256>>>(V, Vh, nV);
    transpose_hilo_kernel<<<dim3(D / 32, S / 32, NB), dim3(32, 8)>>>(V, Vth, Vtl);
    rownorm_kernel<<<(nrows * 32 + 255) / 256, 256>>>(V, v2, D, nrows);

    const dim3 gS(S / 128, S / 128, NB);   // S x S tiles
    const dim3 gD(D / 128, S / 128, NB);   // S x D tiles

    // M0 = A @ V -> Mh + m2 partials (EPI0)
    tc_gemm<D, S, 0, 1, false><<<gD, 256, SMEMB>>>(
        Ah, nullptr, Vth, nullptr, Mh, nullptr, nullptr);

    for (int it = 0; it < 3; ++it) {
        const bool last = (it == 2);
        // W = A / (cdist(M,V)+eps); dot via Mh·Vh; m2 fused in prologue
        if (last)
            tc_gemm<S, D, 1, 1, true><<<gS, 256, SMEMB>>>(
                Mh, nullptr, Vh, nullptr, Wh, Wl, A);
        else
            tc_gemm<S, D, 1, 1, false><<<gS, 256, SMEMB>>>(
                Mh, nullptr, Vh, nullptr, Wh, nullptr, A);
        if (last) {
            // F1 = (Wh + Wl) @ Vh  (2-product, fp32 scratch)
            tc_gemm<D, S, 3, 2, false><<<gD, 256, SMEMB>>>(
                Wh, Wl, Vth, F, nullptr, nullptr, nullptr);
            // F2 = Wh @ Vl; out = (F + F2) * ri  (ri fused in prologue)
            tc_gemm<D, S, 4, 1, false><<<gD, 256, SMEMB>>>(
                Wh, nullptr, Vtl, out, nullptr, nullptr, F);
        } else {
            // M = diag(1/l1) * (W @ V); ri fused in prologue; writes Mh + m2 partials
            tc_gemm<D, S, 2, 1, false><<<gD, 256, SMEMB>>>(
                Wh, nullptr, Vth, nullptr, Mh, nullptr, nullptr);
        }
    }
}

// round 10
// speedup vs baseline: 1.4530x; 1.4530x over previous
#include <cuda_runtime.h>
#include <cuda_bf16.h>
#include <cstdint>
#include <cstddef>

#define S 2048
#define D 512
#define NB 4
#define EPSI 0.01f
#define SWZ(x) ((x) ^ (((x) >> 3) & 0x70))
#define SMEMB (98304 + 2048)

// ---------------- device scratch ----------------
__device__ __align__(128) __nv_bfloat16  g_Ah [(size_t)NB * S * S];
__device__ __align__(128) __nv_bfloat16  g_Wh [(size_t)NB * S * S];
__device__ __align__(128) __nv_bfloat16  g_Wl [(size_t)NB * S * S];
__device__ __align__(128) __nv_bfloat16  g_Mh [(size_t)NB * S * D];
__device__ __align__(128) __nv_bfloat16  g_Vh [(size_t)NB * S * D];
__device__ __align__(128) __nv_bfloat16  g_Vth[(size_t)NB * D * S];
__device__ __align__(128) __nv_bfloat16  g_Vtl[(size_t)NB * D * S];
__device__ __align__(128) float          g_F  [(size_t)NB * S * D];
__device__ __align__(128) float          g_rp [(size_t)NB * 16 * S];
__device__ __align__(128) float          g_mp [(size_t)NB * 4 * S];
__device__ float g_ri[NB * S];
__device__ float g_m2[NB * S];
__device__ float g_v2[NB * S];

// ---------------- PTX helpers (compute_103-safe only) ----------------
__device__ __forceinline__ uint32_t smem_u32(const void* p) {
    uint32_t a;
    asm("{ .reg .u64 t; cvta.to.shared.u64 t, %1; cvt.u32.u64 %0, t; }" : "=r"(a) : "l"(p));
    return a;
}
__device__ __forceinline__ void cpasync16(uint32_t smem, const void* g) {
    asm volatile("cp.async.cg.shared.global [%0], [%1], 16;" :: "r"(smem), "l"(g));
}
__device__ __forceinline__ void cp_commit() {
    asm volatile("cp.async.commit_group;" ::: "memory");
}
template <int N>
__device__ __forceinline__ void cp_wait() {
    asm volatile("cp.async.wait_group %0;" :: "n"(N) : "memory");
}
__device__ __forceinline__ void ldsm4(uint32_t* r, uint32_t addr) {
    asm volatile("ldmatrix.sync.aligned.m8n8.x4.shared.b16 {%0,%1,%2,%3}, [%4];"
                 : "=r"(r[0]), "=r"(r[1]), "=r"(r[2]), "=r"(r[3]) : "r"(addr));
}
__device__ __forceinline__ void mma_bf16(float* c, const uint32_t* a, uint32_t b0, uint32_t b1) {
    asm volatile("mma.sync.aligned.m16n8k16.row.col.f32.bf16.bf16.f32 "
                 "{%0,%1,%2,%3}, {%4,%5,%6,%7}, {%8,%9}, {%0,%1,%2,%3};"
                 : "+f"(c[0]), "+f"(c[1]), "+f"(c[2]), "+f"(c[3])
                 : "r"(a[0]), "r"(a[1]), "r"(a[2]), "r"(a[3]), "r"(b0), "r"(b1));
}
__device__ __forceinline__ unsigned pkb(__nv_bfloat16 a, __nv_bfloat16 b) {
    unsigned short ua = *(unsigned short*)&a, ub = *(unsigned short*)&b;
    return (unsigned)ua | ((unsigned)ub << 16);
}

// ---------------- small kernels ----------------
__global__ void rownorm_kernel(const float* __restrict__ X, float* __restrict__ out,
                               int cols, int nrows) {
    int warp = (blockIdx.x * blockDim.x + threadIdx.x) >> 5;
    int lane = threadIdx.x & 31;
    if (warp >= nrows) return;
    const float* row = X + (size_t)warp * cols;
    float s = 0.f;
    for (int c = lane * 4; c < cols; c += 128) {
        float4 v = *(const float4*)(row + c);
        s += v.x * v.x + v.y * v.y + v.z * v.z + v.w * v.w;
    }
    #pragma unroll
    for (int off = 16; off >= 1; off >>= 1) s += __shfl_xor_sync(0xffffffffu, s, off);
    if (lane == 0) out[warp] = s;
}

__global__ void convert_hi_kernel(const float* __restrict__ X,
                                  __nv_bfloat16* __restrict__ H, size_t n) {
    size_t i = ((size_t)blockIdx.x * blockDim.x + threadIdx.x) * 4;
    if (i >= n) return;
    float4 v = *(const float4*)(X + i);
    *(uint2*)(H + i) = make_uint2(pkb(__float2bfloat16(v.x), __float2bfloat16(v.y)),
                                  pkb(__float2bfloat16(v.z), __float2bfloat16(v.w)));
}

__global__ void transpose_hilo_kernel(const float* __restrict__ V,
                                      __nv_bfloat16* __restrict__ Th,
                                      __nv_bfloat16* __restrict__ Tl) {
    __shared__ float tile[32][33];
    int b = blockIdx.z, d0 = blockIdx.x * 32, j0 = blockIdx.y * 32;
    int tx = threadIdx.x, ty = threadIdx.y;
    #pragma unroll
    for (int r = 0; r < 32; r += 8)
        tile[ty + r][tx] = V[((size_t)b * S + j0 + ty + r) * D + d0 + tx];
    __syncthreads();
    #pragma unroll
    for (int r = 0; r < 32; r += 8) {
        float x = tile[tx][ty + r];
        __nv_bfloat16 h = __float2bfloat16(x);
        size_t o = ((size_t)b * D + d0 + ty + r) * S + j0 + tx;
        Th[o] = h;
        Tl[o] = __float2bfloat16(x - __bfloat162float(h));
    }
}

__global__ void reduce_rinv_kernel() {
    int idx = blockIdx.x * blockDim.x + threadIdx.x;
    if (idx >= NB * S) return;
    int b = idx / S, i = idx - b * S;
    float s = 0.f;
    #pragma unroll
    for (int t = 0; t < 16; ++t) s += g_rp[((size_t)(b * 16 + t)) * S + i];
    g_ri[idx] = 1.0f / fmaxf(s, 1e-12f);
}

__global__ void reduce_m2_kernel() {
    int idx = blockIdx.x * blockDim.x + threadIdx.x;
    if (idx >= NB * S) return;
    int b = idx / S, i = idx - b * S;
    float s = 0.f;
    #pragma unroll
    for (int t = 0; t < 4; ++t) s += g_mp[((size_t)(b * 4 + t)) * S + i];
    g_m2[idx] = s;
}

// ---------------- HMMA GEMM (1-product): C[128,128] = sum_k A[128,k]*B[128,k]^T ----------------
// BK=64, tile rows 64 bf16 (128B), SW128 swizzled. 3 stages x (A 16KB | B 16KB) = 96KB.
// EPI 0: Mh + m2 partials (sc=1)                       [GEMM0]
// EPI 1: weight epilogue -> Wh (+Wl if WLO) + L1 row partials  [GEMM1]
// EPI 2: Mh + m2 partials, sc=ri                       [GEMM2 mid]
// EPI 3: fp32 store -> dstF                            [F  = Wh@Vh]
// EPI 4: dstF = Ain + acc                              [F += Wh@Vl]
// EPI 5: dstF = (Ain + acc) * ri                       [out = (F + Wl@Vh)*ri]
template <int NDIM, int KDIM, int EPI, bool WLO>
__global__ void __launch_bounds__(256, 2)
tc_gemm(const __nv_bfloat16* __restrict__ Ah, const __nv_bfloat16* __restrict__ Bh,
        float* __restrict__ dstF, __nv_bfloat16* __restrict__ dstH,
        __nv_bfloat16* __restrict__ dstL, const float* __restrict__ Ain) {
    extern __shared__ char dsm[];
    const uint32_t sb = smem_u32(dsm);
    float* red = (float*)(dsm + 98304);   // [128][4]

    const int b = blockIdx.z;
    const int mBase = blockIdx.y * 128;
    const int nBase = blockIdx.x * 128;
    const int tid = threadIdx.x;
    const int lane = tid & 31, wid = tid >> 5;
    const int wm = wid & 1, wn = wid >> 1;         // warp tile: M64 x N32

    const int grow_ld = tid >> 1;
    const int hsel = tid & 1;
    const __nv_bfloat16* pAh = Ah + (size_t)b * S * KDIM + (size_t)(mBase + grow_ld) * KDIM;
    const __nv_bfloat16* pBh = Bh + (size_t)b * NDIM * KDIM + (size_t)(nBase + grow_ld) * KDIM;

    const uint32_t rowb = (uint32_t)grow_ld * 128;
    const int nT = KDIM / 64;

    auto load_chunk = [&](int t, int stage) {
        if (t < nT) {
            const int kb = t * 64;
            const uint32_t ab = sb + stage * 16384;
            const uint32_t bb = sb + 49152 + stage * 16384;
            #pragma unroll
            for (int j = 0; j < 4; ++j) {
                const int seg = hsel * 4 + j;
                cpasync16(ab + SWZ(rowb + seg * 16), pAh + kb + seg * 8);
                cpasync16(bb + SWZ(rowb + seg * 16), pBh + kb + seg * 8);
            }
        }
        cp_commit();
    };

    float acc[4][4][4];
    #pragma unroll
    for (int i = 0; i < 4; ++i)
        #pragma unroll
        for (int j = 0; j < 4; ++j)
            #pragma unroll
            for (int e = 0; e < 4; ++e) acc[i][j][e] = 0.f;

    load_chunk(0, 0);
    load_chunk(1, 1);

    const int lrow = lane & 15, cseg = lane >> 4;

    int buf = 0, sld = 2;
    for (int t = 0; t < nT; ++t) {
        cp_wait<1>();
        __syncthreads();
        load_chunk(t + 2, sld);

        const uint32_t ab = sb + buf * 16384;
        const uint32_t bb = sb + 49152 + buf * 16384;

        #pragma unroll
        for (int s = 0; s < 4; ++s) {
            const uint32_t kcol = (uint32_t)(s * 2 + cseg) * 16;
            uint32_t bfh[2][4];
            #pragma unroll
            for (int g = 0; g < 2; ++g) {
                const uint32_t br = (uint32_t)(wn * 32 + g * 16 + lrow) * 128;
                ldsm4(bfh[g], bb + SWZ(br + kcol));
            }
            uint32_t afh[4][4];
            #pragma unroll
            for (int mf = 0; mf < 4; ++mf) {
                const uint32_t arr = (uint32_t)(wm * 64 + mf * 16 + lrow) * 128;
                ldsm4(afh[mf], ab + SWZ(arr + kcol));
            }
            #pragma unroll
            for (int mf = 0; mf < 4; ++mf)
                #pragma unroll
                for (int nf = 0; nf < 4; ++nf) {
                    const int g = nf >> 1, h = nf & 1;
                    mma_bf16(acc[mf][nf], afh[mf], bfh[g][h], bfh[g][h + 2]);
                }
        }
        buf = (buf == 2) ? 0 : buf + 1;
        sld = (sld == 2) ? 0 : sld + 1;
    }

    // ---------------- epilogue ----------------
    const int q = lane >> 2, tq = lane & 3;

    if (EPI == 1) {
        float v2c[4][2];
        #pragma unroll
        for (int nf = 0; nf < 4; ++nf) {
            float2 v2v = *(const float2*)(g_v2 + b * S + nBase + wn * 32 + nf * 8 + tq * 2);
            v2c[nf][0] = v2v.x; v2c[nf][1] = v2v.y;
        }
        #pragma unroll
        for (int mf = 0; mf < 4; ++mf) {
            #pragma unroll
            for (int r2 = 0; r2 < 2; ++r2) {
                const int lr = wm * 64 + mf * 16 + q + r2 * 8;
                const int gr = mBase + lr;
                const float m2v = g_m2[b * S + gr];
                const float* arow = Ain + ((size_t)b * S + gr) * S + nBase + wn * 32;
                __nv_bfloat16* whp = dstH + ((size_t)b * S + gr) * S + nBase + wn * 32;
                __nv_bfloat16* wlp = WLO ? dstL + ((size_t)b * S + gr) * S + nBase + wn * 32 : nullptr;
                float rs = 0.f;
                #pragma unroll
                for (int nf = 0; nf < 4; ++nf) {
                    float2 a2 = *(const float2*)(arow + nf * 8 + tq * 2);
                    float d2 = fmaxf(m2v + v2c[nf][0] - 2.f * acc[mf][nf][r2 * 2], 0.f);
                    float w0 = __fdividef(a2.x, sqrtf(d2) + EPSI);
                    d2 = fmaxf(m2v + v2c[nf][1] - 2.f * acc[mf][nf][r2 * 2 + 1], 0.f);
                    float w1 = __fdividef(a2.y, sqrtf(d2) + EPSI);
                    rs += fabsf(w0) + fabsf(w1);
                    __nv_bfloat16 h0 = __float2bfloat16(w0), h1 = __float2bfloat16(w1);
                    *(unsigned*)(whp + nf * 8 + tq * 2) = pkb(h0, h1);
                    if (WLO)
                        *(unsigned*)(wlp + nf * 8 + tq * 2) =
                            pkb(__float2bfloat16(w0 - __bfloat162float(h0)),
                                __float2bfloat16(w1 - __bfloat162float(h1)));
                }
                rs += __shfl_xor_sync(0xffffffffu, rs, 1);
                rs += __shfl_xor_sync(0xffffffffu, rs, 2);
                if (tq == 0) red[lr * 4 + wn] = rs;
            }
        }
        __syncthreads();
        if (tid < 128) {
            float s = red[tid * 4] + red[tid * 4 + 1] + red[tid * 4 + 2] + red[tid * 4 + 3];
            g_rp[((size_t)(b * 16 + blockIdx.x)) * S + mBase + tid] = s;
        }
    } else if (EPI == 3) {
        #pragma unroll
        for (int mf = 0; mf < 4; ++mf) {
            #pragma unroll
            for (int r2 = 0; r2 < 2; ++r2) {
                const int gr = mBase + wm * 64 + mf * 16 + q + r2 * 8;
                float* fo = dstF + ((size_t)b * S + gr) * NDIM + nBase + wn * 32;
                #pragma unroll
                for (int nf = 0; nf < 4; ++nf)
                    *(float2*)(fo + nf * 8 + tq * 2) =
                        make_float2(acc[mf][nf][r2 * 2], acc[mf][nf][r2 * 2 + 1]);
            }
        }
    } else if (EPI == 4 || EPI == 5) {
        #pragma unroll
        for (int mf = 0; mf < 4; ++mf) {
            #pragma unroll
            for (int r2 = 0; r2 < 2; ++r2) {
                const int gr = mBase + wm * 64 + mf * 16 + q + r2 * 8;
                const float sc = (EPI == 5) ? g_ri[b * S + gr] : 1.f;
                const float* fi = Ain + ((size_t)b * S + gr) * NDIM + nBase + wn * 32;
                float* fo = dstF + ((size_t)b * S + gr) * NDIM + nBase + wn * 32;
                #pragma unroll
                for (int nf = 0; nf < 4; ++nf) {
                    float2 pv = *(const float2*)(fi + nf * 8 + tq * 2);
                    *(float2*)(fo + nf * 8 + tq * 2) =
                        make_float2((pv.x + acc[mf][nf][r2 * 2]) * sc,
                                    (pv.y + acc[mf][nf][r2 * 2 + 1]) * sc);
                }
            }
        }
    } else {
        // EPI 0 / 2: bf16 Mh store + m2 partials
        #pragma unroll
        for (int mf = 0; mf < 4; ++mf) {
            #pragma unroll
            for (int r2 = 0; r2 < 2; ++r2) {
                const int lr = wm * 64 + mf * 16 + q + r2 * 8;
                const int gr = mBase + lr;
                const float sc = (EPI == 2) ? g_ri[b * S + gr] : 1.f;
                __nv_bfloat16* hp = dstH + ((size_t)b * S + gr) * NDIM + nBase + wn * 32;
                float rs = 0.f;
                #pragma unroll
                for (int nf = 0; nf < 4; ++nf) {
                    float o0 = acc[mf][nf][r2 * 2] * sc;
                    float o1 = acc[mf][nf][r2 * 2 + 1] * sc;
                    rs += o0 * o0 + o1 * o1;
                    *(unsigned*)(hp + nf * 8 + tq * 2) =
                        pkb(__float2bfloat16(o0), __float2bfloat16(o1));
                }
                rs += __shfl_xor_sync(0xffffffffu, rs, 1);
                rs += __shfl_xor_sync(0xffffffffu, rs, 2);
                if (tq == 0) red[lr * 4 + wn] = rs;
            }
        }
        __syncthreads();
        if (tid < 128) {
            float s = red[tid * 4] + red[tid * 4 + 1] + red[tid * 4 + 2] + red[tid * 4 + 3];
            g_mp[((size_t)(b * 4 + blockIdx.x)) * S + mBase + tid] = s;
        }
    }
}

// ---------------- launch ----------------
extern "C" void kernel_launch(void* const* d_in, const int* in_sizes, int n_in,
                              void* d_out, int out_size) {
    const float* A = (const float*)d_in[0];
    const float* V = (const float*)d_in[1];
    float* out = (float*)d_out;

    void* p;
    cudaGetSymbolAddress(&p, g_Ah);  __nv_bfloat16* Ah = (__nv_bfloat16*)p;
    cudaGetSymbolAddress(&p, g_Wh);  __nv_bfloat16* Wh = (__nv_bfloat16*)p;
    cudaGetSymbolAddress(&p, g_Wl);  __nv_bfloat16* Wl = (__nv_bfloat16*)p;
    cudaGetSymbolAddress(&p, g_Mh);  __nv_bfloat16* Mh = (__nv_bfloat16*)p;
    cudaGetSymbolAddress(&p, g_Vh);  __nv_bfloat16* Vh = (__nv_bfloat16*)p;
    cudaGetSymbolAddress(&p, g_Vth); __nv_bfloat16* Vth = (__nv_bfloat16*)p;
    cudaGetSymbolAddress(&p, g_Vtl); __nv_bfloat16* Vtl = (__nv_bfloat16*)p;
    cudaGetSymbolAddress(&p, g_F);   float* F = (float*)p;
    cudaGetSymbolAddress(&p, g_v2);  float* v2 = (float*)p;

    cudaFuncSetAttribute(tc_gemm<D, S, 0, false>, cudaFuncAttributeMaxDynamicSharedMemorySize, SMEMB);
    cudaFuncSetAttribute(tc_gemm<S, D, 1, false>, cudaFuncAttributeMaxDynamicSharedMemorySize, SMEMB);
    cudaFuncSetAttribute(tc_gemm<S, D, 1, true>,  cudaFuncAttributeMaxDynamicSharedMemorySize, SMEMB);
    cudaFuncSetAttribute(tc_gemm<D, S, 2, false>, cudaFuncAttributeMaxDynamicSharedMemorySize, SMEMB);
    cudaFuncSetAttribute(tc_gemm<D, S, 3, false>, cudaFuncAttributeMaxDynamicSharedMemorySize, SMEMB);
    cudaFuncSetAttribute(tc_gemm<D, S, 4, false>, cudaFuncAttributeMaxDynamicSharedMemorySize, SMEMB);
    cudaFuncSetAttribute(tc_gemm<D, S, 5, false>, cudaFuncAttributeMaxDynamicSharedMemorySize, SMEMB);

    const int nrows = NB * S;
    const size_t nA = (size_t)NB * S * S;
    const size_t nV = (size_t)NB * S * D;

    convert_hi_kernel<<<(unsigned)((nA / 4 + 255) / 256), 256>>>(A, Ah, nA);
    convert_hi_kernel<<<(unsigned)((nV / 4 + 255) / 256), 256>>>(V, Vh, nV);
    transpose_hilo_kernel<<<dim3(D / 32, S / 32, NB), dim3(32, 8)>>>(V, Vth, Vtl);
    rownorm_kernel<<<(nrows * 32 + 255) / 256, 256>>>(V, v2, D, nrows);

    const dim3 gS(S / 128, S / 128, NB);
    const dim3 gD(D / 128, S / 128, NB);

    // M0 = A @ V -> Mh + m2 partials
    tc_gemm<D, S, 0, false><<<gD, 256, SMEMB>>>(Ah, Vth, nullptr, Mh, nullptr, nullptr);
    reduce_m2_kernel<<<(NB * S + 255) / 256, 256>>>();

    for (int it = 0; it < 3; ++it) {
        const bool last = (it == 2);
        // W = A / (cdist(M,V)+eps); dot via Mh·Vh
        if (last)
            tc_gemm<S, D, 1, true><<<gS, 256, SMEMB>>>(Mh, Vh, nullptr, Wh, Wl, A);
        else
            tc_gemm<S, D, 1, false><<<gS, 256, SMEMB>>>(Mh, Vh, nullptr, Wh, nullptr, A);
        reduce_rinv_kernel<<<(NB * S + 255) / 256, 256>>>();

        if (last) {
            // out = ri * (Wh@Vh + Wh@Vl + Wl@Vh), via fp32 scratch F
            tc_gemm<D, S, 3, false><<<gD, 256, SMEMB>>>(Wh, Vth, F,   nullptr, nullptr, nullptr);
            tc_gemm<D, S, 4, false><<<gD, 256, SMEMB>>>(Wh, Vtl, F,   nullptr, nullptr, F);
            tc_gemm<D, S, 5, false><<<gD, 256, SMEMB>>>(Wl, Vth, out, nullptr, nullptr, F);
        } else {
            // M = diag(1/l1) * (W @ V) -> Mh + m2 partials
            tc_gemm<D, S, 2, false><<<gD, 256, SMEMB>>>(Wh, Vth, nullptr, Mh, nullptr, nullptr);
            reduce_m2_kernel<<<(NB * S + 255) / 256, 256>>>();
        }
    }
}

// round 11
// speedup vs baseline: 1.4725x; 1.0135x over previous
#include <cuda_runtime.h>
#include <cuda_bf16.h>
#include <cstdint>
#include <cstddef>

#define S 2048
#define D 512
#define NB 4
#define EPSI 0.01f
#define SWZ(x) ((x) ^ (((x) >> 3) & 0x70))
#define SMEMB (98304 + 2048)

// ---------------- device scratch ----------------
__device__ __align__(128) __nv_bfloat16  g_Ah [(size_t)NB * S * S];
__device__ __align__(128) __nv_bfloat16  g_Wh [(size_t)NB * S * S];
__device__ __align__(128) __nv_bfloat16  g_Wl [(size_t)NB * S * S];
__device__ __align__(128) __nv_bfloat16  g_Mh [(size_t)NB * S * D];
__device__ __align__(128) __nv_bfloat16  g_Vh [(size_t)NB * S * D];
__device__ __align__(128) __nv_bfloat16  g_Vth[(size_t)NB * D * S];
__device__ __align__(128) __nv_bfloat16  g_Vtl[(size_t)NB * D * S];
__device__ __align__(128) float          g_rp [(size_t)NB * 16 * S];
__device__ __align__(128) float          g_mp [(size_t)NB * 4 * S];
__device__ float g_ri[NB * S];
__device__ float g_m2[NB * S];
__device__ float g_v2[NB * S];

// ---------------- PTX helpers (compute_103-safe only) ----------------
__device__ __forceinline__ uint32_t smem_u32(const void* p) {
    uint32_t a;
    asm("{ .reg .u64 t; cvta.to.shared.u64 t, %1; cvt.u32.u64 %0, t; }" : "=r"(a) : "l"(p));
    return a;
}
__device__ __forceinline__ void cpasync16(uint32_t smem, const void* g) {
    asm volatile("cp.async.cg.shared.global [%0], [%1], 16;" :: "r"(smem), "l"(g));
}
__device__ __forceinline__ void cp_commit() {
    asm volatile("cp.async.commit_group;" ::: "memory");
}
template <int N>
__device__ __forceinline__ void cp_wait() {
    asm volatile("cp.async.wait_group %0;" :: "n"(N) : "memory");
}
__device__ __forceinline__ void ldsm4(uint32_t* r, uint32_t addr) {
    asm volatile("ldmatrix.sync.aligned.m8n8.x4.shared.b16 {%0,%1,%2,%3}, [%4];"
                 : "=r"(r[0]), "=r"(r[1]), "=r"(r[2]), "=r"(r[3]) : "r"(addr));
}
__device__ __forceinline__ void mma_bf16(float* c, const uint32_t* a, uint32_t b0, uint32_t b1) {
    asm volatile("mma.sync.aligned.m16n8k16.row.col.f32.bf16.bf16.f32 "
                 "{%0,%1,%2,%3}, {%4,%5,%6,%7}, {%8,%9}, {%0,%1,%2,%3};"
                 : "+f"(c[0]), "+f"(c[1]), "+f"(c[2]), "+f"(c[3])
                 : "r"(a[0]), "r"(a[1]), "r"(a[2]), "r"(a[3]), "r"(b0), "r"(b1));
}
__device__ __forceinline__ unsigned pkb(__nv_bfloat16 a, __nv_bfloat16 b) {
    unsigned short ua = *(unsigned short*)&a, ub = *(unsigned short*)&b;
    return (unsigned)ua | ((unsigned)ub << 16);
}

// ---------------- small kernels ----------------
__global__ void rownorm_kernel(const float* __restrict__ X, float* __restrict__ out,
                               int cols, int nrows) {
    int warp = (blockIdx.x * blockDim.x + threadIdx.x) >> 5;
    int lane = threadIdx.x & 31;
    if (warp >= nrows) return;
    const float* row = X + (size_t)warp * cols;
    float s = 0.f;
    for (int c = lane * 4; c < cols; c += 128) {
        float4 v = *(const float4*)(row + c);
        s += v.x * v.x + v.y * v.y + v.z * v.z + v.w * v.w;
    }
    #pragma unroll
    for (int off = 16; off >= 1; off >>= 1) s += __shfl_xor_sync(0xffffffffu, s, off);
    if (lane == 0) out[warp] = s;
}

__global__ void convert_hi_kernel(const float* __restrict__ X,
                                  __nv_bfloat16* __restrict__ H, size_t n) {
    size_t i = ((size_t)blockIdx.x * blockDim.x + threadIdx.x) * 4;
    if (i >= n) return;
    float4 v = *(const float4*)(X + i);
    *(uint2*)(H + i) = make_uint2(pkb(__float2bfloat16(v.x), __float2bfloat16(v.y)),
                                  pkb(__float2bfloat16(v.z), __float2bfloat16(v.w)));
}

__global__ void transpose_hilo_kernel(const float* __restrict__ V,
                                      __nv_bfloat16* __restrict__ Th,
                                      __nv_bfloat16* __restrict__ Tl) {
    __shared__ float tile[32][33];
    int b = blockIdx.z, d0 = blockIdx.x * 32, j0 = blockIdx.y * 32;
    int tx = threadIdx.x, ty = threadIdx.y;
    #pragma unroll
    for (int r = 0; r < 32; r += 8)
        tile[ty + r][tx] = V[((size_t)b * S + j0 + ty + r) * D + d0 + tx];
    __syncthreads();
    #pragma unroll
    for (int r = 0; r < 32; r += 8) {
        float x = tile[tx][ty + r];
        __nv_bfloat16 h = __float2bfloat16(x);
        size_t o = ((size_t)b * D + d0 + ty + r) * S + j0 + tx;
        Th[o] = h;
        Tl[o] = __float2bfloat16(x - __bfloat162float(h));
    }
}

__global__ void reduce_rinv_kernel() {
    int idx = blockIdx.x * blockDim.x + threadIdx.x;
    if (idx >= NB * S) return;
    int b = idx / S, i = idx - b * S;
    float s = 0.f;
    #pragma unroll
    for (int t = 0; t < 16; ++t) s += g_rp[((size_t)(b * 16 + t)) * S + i];
    g_ri[idx] = 1.0f / fmaxf(s, 1e-12f);
}

__global__ void reduce_m2_kernel() {
    int idx = blockIdx.x * blockDim.x + threadIdx.x;
    if (idx >= NB * S) return;
    int b = idx / S, i = idx - b * S;
    float s = 0.f;
    #pragma unroll
    for (int t = 0; t < 4; ++t) s += g_mp[((size_t)(b * 4 + t)) * S + i];
    g_m2[idx] = s;
}

// ---------------- HMMA GEMM (1-product): C[128,128] = sum_k A[128,k]*B[128,k]^T ----------------
// BK=64, tile rows 64 bf16 (128B), SW128 swizzled. 3 stages x (A 16KB | B 16KB) = 96KB.
// EPI 0: Mh + m2 partials (sc=1)                       [GEMM0]
// EPI 1: weight epilogue -> Wh (+Wl if WLO) + L1 row partials  [GEMM1]
// EPI 2: Mh + m2 partials, sc=ri                       [GEMM2 mid]
// EPI 3: CONCAT-K (3 segments: Ah@Bh + Ah@B2 + A2@Bh), out = acc*ri -> dstF  [final]
template <int NDIM, int KDIM, int EPI, bool WLO>
__global__ void __launch_bounds__(256, 2)
tc_gemm(const __nv_bfloat16* __restrict__ Ah, const __nv_bfloat16* __restrict__ A2,
        const __nv_bfloat16* __restrict__ Bh, const __nv_bfloat16* __restrict__ B2,
        float* __restrict__ dstF, __nv_bfloat16* __restrict__ dstH,
        __nv_bfloat16* __restrict__ dstL, const float* __restrict__ Ain) {
    extern __shared__ char dsm[];
    const uint32_t sb = smem_u32(dsm);
    float* red = (float*)(dsm + 98304);   // [128][4]

    const int b = blockIdx.z;
    const int mBase = blockIdx.y * 128;
    const int nBase = blockIdx.x * 128;
    const int tid = threadIdx.x;
    const int lane = tid & 31, wid = tid >> 5;
    const int wm = wid & 1, wn = wid >> 1;         // warp tile: M64 x N32

    const int grow_ld = tid >> 1;
    const int hsel = tid & 1;
    const size_t aoff = (size_t)b * S * KDIM + (size_t)(mBase + grow_ld) * KDIM;
    const size_t boff = (size_t)b * NDIM * KDIM + (size_t)(nBase + grow_ld) * KDIM;
    const __nv_bfloat16* pAh = Ah + aoff;
    const __nv_bfloat16* pA2 = (EPI == 3) ? A2 + aoff : nullptr;
    const __nv_bfloat16* pBh = Bh + boff;
    const __nv_bfloat16* pB2 = (EPI == 3) ? B2 + boff : nullptr;

    const uint32_t rowb = (uint32_t)grow_ld * 128;
    constexpr int CPS = KDIM / 64;                    // chunks per K segment
    const int nT = (EPI == 3) ? 3 * CPS : CPS;

    auto load_chunk = [&](int t, int stage) {
        if (t < nT) {
            const __nv_bfloat16* pa = pAh;
            const __nv_bfloat16* pb = pBh;
            int kb;
            if (EPI == 3) {
                const int seg = t / CPS;
                kb = (t - seg * CPS) * 64;
                if (seg == 2) pa = pA2;      // Wl @ Vh
                if (seg == 1) pb = pB2;      // Wh @ Vl
            } else {
                kb = t * 64;
            }
            const uint32_t ab = sb + stage * 16384;
            const uint32_t bb = sb + 49152 + stage * 16384;
            #pragma unroll
            for (int j = 0; j < 4; ++j) {
                const int seg = hsel * 4 + j;
                cpasync16(ab + SWZ(rowb + seg * 16), pa + kb + seg * 8);
                cpasync16(bb + SWZ(rowb + seg * 16), pb + kb + seg * 8);
            }
        }
        cp_commit();
    };

    float acc[4][4][4];
    #pragma unroll
    for (int i = 0; i < 4; ++i)
        #pragma unroll
        for (int j = 0; j < 4; ++j)
            #pragma unroll
            for (int e = 0; e < 4; ++e) acc[i][j][e] = 0.f;

    load_chunk(0, 0);
    load_chunk(1, 1);

    const int lrow = lane & 15, cseg = lane >> 4;

    int buf = 0, sld = 2;
    for (int t = 0; t < nT; ++t) {
        cp_wait<1>();
        __syncthreads();
        load_chunk(t + 2, sld);

        const uint32_t ab = sb + buf * 16384;
        const uint32_t bb = sb + 49152 + buf * 16384;

        #pragma unroll
        for (int s = 0; s < 4; ++s) {
            const uint32_t kcol = (uint32_t)(s * 2 + cseg) * 16;
            uint32_t bfh[2][4];
            #pragma unroll
            for (int g = 0; g < 2; ++g) {
                const uint32_t br = (uint32_t)(wn * 32 + g * 16 + lrow) * 128;
                ldsm4(bfh[g], bb + SWZ(br + kcol));
            }
            uint32_t afh[4][4];
            #pragma unroll
            for (int mf = 0; mf < 4; ++mf) {
                const uint32_t arr = (uint32_t)(wm * 64 + mf * 16 + lrow) * 128;
                ldsm4(afh[mf], ab + SWZ(arr + kcol));
            }
            #pragma unroll
            for (int mf = 0; mf < 4; ++mf)
                #pragma unroll
                for (int nf = 0; nf < 4; ++nf) {
                    const int g = nf >> 1, h = nf & 1;
                    mma_bf16(acc[mf][nf], afh[mf], bfh[g][h], bfh[g][h + 2]);
                }
        }
        buf = (buf == 2) ? 0 : buf + 1;
        sld = (sld == 2) ? 0 : sld + 1;
    }

    // ---------------- epilogue ----------------
    const int q = lane >> 2, tq = lane & 3;

    if (EPI == 1) {
        float v2c[4][2];
        #pragma unroll
        for (int nf = 0; nf < 4; ++nf) {
            float2 v2v = *(const float2*)(g_v2 + b * S + nBase + wn * 32 + nf * 8 + tq * 2);
            v2c[nf][0] = v2v.x; v2c[nf][1] = v2v.y;
        }
        #pragma unroll
        for (int mf = 0; mf < 4; ++mf) {
            #pragma unroll
            for (int r2 = 0; r2 < 2; ++r2) {
                const int lr = wm * 64 + mf * 16 + q + r2 * 8;
                const int gr = mBase + lr;
                const float m2v = g_m2[b * S + gr];
                const float* arow = Ain + ((size_t)b * S + gr) * S + nBase + wn * 32;
                __nv_bfloat16* whp = dstH + ((size_t)b * S + gr) * S + nBase + wn * 32;
                __nv_bfloat16* wlp = WLO ? dstL + ((size_t)b * S + gr) * S + nBase + wn * 32 : nullptr;
                float rs = 0.f;
                #pragma unroll
                for (int nf = 0; nf < 4; ++nf) {
                    float2 a2 = *(const float2*)(arow + nf * 8 + tq * 2);
                    float d2 = fmaxf(m2v + v2c[nf][0] - 2.f * acc[mf][nf][r2 * 2], 0.f);
                    float w0 = __fdividef(a2.x, sqrtf(d2) + EPSI);
                    d2 = fmaxf(m2v + v2c[nf][1] - 2.f * acc[mf][nf][r2 * 2 + 1], 0.f);
                    float w1 = __fdividef(a2.y, sqrtf(d2) + EPSI);
                    rs += fabsf(w0) + fabsf(w1);
                    __nv_bfloat16 h0 = __float2bfloat16(w0), h1 = __float2bfloat16(w1);
                    *(unsigned*)(whp + nf * 8 + tq * 2) = pkb(h0, h1);
                    if (WLO)
                        *(unsigned*)(wlp + nf * 8 + tq * 2) =
                            pkb(__float2bfloat16(w0 - __bfloat162float(h0)),
                                __float2bfloat16(w1 - __bfloat162float(h1)));
                }
                rs += __shfl_xor_sync(0xffffffffu, rs, 1);
                rs += __shfl_xor_sync(0xffffffffu, rs, 2);
                if (tq == 0) red[lr * 4 + wn] = rs;
            }
        }
        __syncthreads();
        if (tid < 128) {
            float s = red[tid * 4] + red[tid * 4 + 1] + red[tid * 4 + 2] + red[tid * 4 + 3];
            g_rp[((size_t)(b * 16 + blockIdx.x)) * S + mBase + tid] = s;
        }
    } else if (EPI == 3) {
        #pragma unroll
        for (int mf = 0; mf < 4; ++mf) {
            #pragma unroll
            for (int r2 = 0; r2 < 2; ++r2) {
                const int gr = mBase + wm * 64 + mf * 16 + q + r2 * 8;
                const float sc = g_ri[b * S + gr];
                float* fo = dstF + ((size_t)b * S + gr) * NDIM + nBase + wn * 32;
                #pragma unroll
                for (int nf = 0; nf < 4; ++nf)
                    *(float2*)(fo + nf * 8 + tq * 2) =
                        make_float2(acc[mf][nf][r2 * 2] * sc, acc[mf][nf][r2 * 2 + 1] * sc);
            }
        }
    } else {
        // EPI 0 / 2: bf16 Mh store + m2 partials
        #pragma unroll
        for (int mf = 0; mf < 4; ++mf) {
            #pragma unroll
            for (int r2 = 0; r2 < 2; ++r2) {
                const int lr = wm * 64 + mf * 16 + q + r2 * 8;
                const int gr = mBase + lr;
                const float sc = (EPI == 2) ? g_ri[b * S + gr] : 1.f;
                __nv_bfloat16* hp = dstH + ((size_t)b * S + gr) * NDIM + nBase + wn * 32;
                float rs = 0.f;
                #pragma unroll
                for (int nf = 0; nf < 4; ++nf) {
                    float o0 = acc[mf][nf][r2 * 2] * sc;
                    float o1 = acc[mf][nf][r2 * 2 + 1] * sc;
                    rs += o0 * o0 + o1 * o1;
                    *(unsigned*)(hp + nf * 8 + tq * 2) =
                        pkb(__float2bfloat16(o0), __float2bfloat16(o1));
                }
                rs += __shfl_xor_sync(0xffffffffu, rs, 1);
                rs += __shfl_xor_sync(0xffffffffu, rs, 2);
                if (tq == 0) red[lr * 4 + wn] = rs;
            }
        }
        __syncthreads();
        if (tid < 128) {
            float s = red[tid * 4] + red[tid * 4 + 1] + red[tid * 4 + 2] + red[tid * 4 + 3];
            g_mp[((size_t)(b * 4 + blockIdx.x)) * S + mBase + tid] = s;
        }
    }
}

// ---------------- launch ----------------
extern "C" void kernel_launch(void* const* d_in, const int* in_sizes, int n_in,
                              void* d_out, int out_size) {
    const float* A = (const float*)d_in[0];
    const float* V = (const float*)d_in[1];
    float* out = (float*)d_out;

    void* p;
    cudaGetSymbolAddress(&p, g_Ah);  __nv_bfloat16* Ah = (__nv_bfloat16*)p;
    cudaGetSymbolAddress(&p, g_Wh);  __nv_bfloat16* Wh = (__nv_bfloat16*)p;
    cudaGetSymbolAddress(&p, g_Wl);  __nv_bfloat16* Wl = (__nv_bfloat16*)p;
    cudaGetSymbolAddress(&p, g_Mh);  __nv_bfloat16* Mh = (__nv_bfloat16*)p;
    cudaGetSymbolAddress(&p, g_Vh);  __nv_bfloat16* Vh = (__nv_bfloat16*)p;
    cudaGetSymbolAddress(&p, g_Vth); __nv_bfloat16* Vth = (__nv_bfloat16*)p;
    cudaGetSymbolAddress(&p, g_Vtl); __nv_bfloat16* Vtl = (__nv_bfloat16*)p;
    cudaGetSymbolAddress(&p, g_v2);  float* v2 = (float*)p;

    cudaFuncSetAttribute(tc_gemm<D, S, 0, false>, cudaFuncAttributeMaxDynamicSharedMemorySize, SMEMB);
    cudaFuncSetAttribute(tc_gemm<S, D, 1, false>, cudaFuncAttributeMaxDynamicSharedMemorySize, SMEMB);
    cudaFuncSetAttribute(tc_gemm<S, D, 1, true>,  cudaFuncAttributeMaxDynamicSharedMemorySize, SMEMB);
    cudaFuncSetAttribute(tc_gemm<D, S, 2, false>, cudaFuncAttributeMaxDynamicSharedMemorySize, SMEMB);
    cudaFuncSetAttribute(tc_gemm<D, S, 3, false>, cudaFuncAttributeMaxDynamicSharedMemorySize, SMEMB);

    const int nrows = NB * S;
    const size_t nA = (size_t)NB * S * S;
    const size_t nV = (size_t)NB * S * D;

    convert_hi_kernel<<<(unsigned)((nA / 4 + 255) / 256), 256>>>(A, Ah, nA);
    convert_hi_kernel<<<(unsigned)((nV / 4 + 255) / 256), 256>>>(V, Vh, nV);
    transpose_hilo_kernel<<<dim3(D / 32, S / 32, NB), dim3(32, 8)>>>(V, Vth, Vtl);
    rownorm_kernel<<<(nrows * 32 + 255) / 256, 256>>>(V, v2, D, nrows);

    const dim3 gS(S / 128, S / 128, NB);
    const dim3 gD(D / 128, S / 128, NB);

    // M0 = A @ V -> Mh + m2 partials
    tc_gemm<D, S, 0, false><<<gD, 256, SMEMB>>>(Ah, nullptr, Vth, nullptr,
                                                nullptr, Mh, nullptr, nullptr);
    reduce_m2_kernel<<<(NB * S + 255) / 256, 256>>>();

    for (int it = 0; it < 3; ++it) {
        const bool last = (it == 2);
        // W = A / (cdist(M,V)+eps); dot via Mh·Vh
        if (last)
            tc_gemm<S, D, 1, true><<<gS, 256, SMEMB>>>(Mh, nullptr, Vh, nullptr,
                                                       nullptr, Wh, Wl, A);
        else
            tc_gemm<S, D, 1, false><<<gS, 256, SMEMB>>>(Mh, nullptr, Vh, nullptr,
                                                        nullptr, Wh, nullptr, A);
        reduce_rinv_kernel<<<(NB * S + 255) / 256, 256>>>();

        if (last) {
            // out = ri * (Wh@Vh + Wh@Vl + Wl@Vh) — single concat-K kernel
            tc_gemm<D, S, 3, false><<<gD, 256, SMEMB>>>(Wh, Wl, Vth, Vtl,
                                                        out, nullptr, nullptr, nullptr);
        } else {
            // M = diag(1/l1) * (W @ V) -> Mh + m2 partials
            tc_gemm<D, S, 2, false><<<gD, 256, SMEMB>>>(Wh, nullptr, Vth, nullptr,
                                                        nullptr, Mh, nullptr, nullptr);
            reduce_m2_kernel<<<(NB * S + 255) / 256, 256>>>();
        }
    }
}

// round 12
// speedup vs baseline: 1.4960x; 1.0159x over previous
#include <cuda_runtime.h>
#include <cuda_bf16.h>
#include <cstdint>
#include <cstddef>

#define S 2048
#define D 512
#define NB 4
#define EPSI 0.01f
#define SWZ(x) ((x) ^ (((x) >> 3) & 0x70))
#define SMEMB (98304 + 2048)
#define SMEMB3 (196608 + 1024)

// ---------------- device scratch ----------------
__device__ __align__(128) __nv_bfloat16  g_Ah [(size_t)NB * S * S];
__device__ __align__(128) __nv_bfloat16  g_Wh [(size_t)NB * S * S];
__device__ __align__(128) __nv_bfloat16  g_Wl [(size_t)NB * S * S];
__device__ __align__(128) __nv_bfloat16  g_Mh [(size_t)NB * S * D];
__device__ __align__(128) __nv_bfloat16  g_Vh [(size_t)NB * S * D];
__device__ __align__(128) __nv_bfloat16  g_Vth[(size_t)NB * D * S];
__device__ __align__(128) __nv_bfloat16  g_Vtl[(size_t)NB * D * S];
__device__ __align__(128) float          g_rp [(size_t)NB * 16 * S];
__device__ __align__(128) float          g_mp [(size_t)NB * 4 * S];
__device__ float g_ri[NB * S];
__device__ float g_m2[NB * S];
__device__ float g_v2[NB * S];

// ---------------- PTX helpers (compute_103-safe only) ----------------
__device__ __forceinline__ uint32_t smem_u32(const void* p) {
    uint32_t a;
    asm("{ .reg .u64 t; cvta.to.shared.u64 t, %1; cvt.u32.u64 %0, t; }" : "=r"(a) : "l"(p));
    return a;
}
__device__ __forceinline__ void cpasync16(uint32_t smem, const void* g) {
    asm volatile("cp.async.cg.shared.global [%0], [%1], 16;" :: "r"(smem), "l"(g));
}
__device__ __forceinline__ void cp_commit() {
    asm volatile("cp.async.commit_group;" ::: "memory");
}
template <int N>
__device__ __forceinline__ void cp_wait() {
    asm volatile("cp.async.wait_group %0;" :: "n"(N) : "memory");
}
__device__ __forceinline__ void ldsm4(uint32_t* r, uint32_t addr) {
    asm volatile("ldmatrix.sync.aligned.m8n8.x4.shared.b16 {%0,%1,%2,%3}, [%4];"
                 : "=r"(r[0]), "=r"(r[1]), "=r"(r[2]), "=r"(r[3]) : "r"(addr));
}
__device__ __forceinline__ void mma_bf16(float* c, const uint32_t* a, uint32_t b0, uint32_t b1) {
    asm volatile("mma.sync.aligned.m16n8k16.row.col.f32.bf16.bf16.f32 "
                 "{%0,%1,%2,%3}, {%4,%5,%6,%7}, {%8,%9}, {%0,%1,%2,%3};"
                 : "+f"(c[0]), "+f"(c[1]), "+f"(c[2]), "+f"(c[3])
                 : "r"(a[0]), "r"(a[1]), "r"(a[2]), "r"(a[3]), "r"(b0), "r"(b1));
}
__device__ __forceinline__ unsigned pkb(__nv_bfloat16 a, __nv_bfloat16 b) {
    unsigned short ua = *(unsigned short*)&a, ub = *(unsigned short*)&b;
    return (unsigned)ua | ((unsigned)ub << 16);
}

// ---------------- small kernels ----------------
__global__ void rownorm_kernel(const float* __restrict__ X, float* __restrict__ out,
                               int cols, int nrows) {
    int warp = (blockIdx.x * blockDim.x + threadIdx.x) >> 5;
    int lane = threadIdx.x & 31;
    if (warp >= nrows) return;
    const float* row = X + (size_t)warp * cols;
    float s = 0.f;
    for (int c = lane * 4; c < cols; c += 128) {
        float4 v = *(const float4*)(row + c);
        s += v.x * v.x + v.y * v.y + v.z * v.z + v.w * v.w;
    }
    #pragma unroll
    for (int off = 16; off >= 1; off >>= 1) s += __shfl_xor_sync(0xffffffffu, s, off);
    if (lane == 0) out[warp] = s;
}

__global__ void convert_hi_kernel(const float* __restrict__ X,
                                  __nv_bfloat16* __restrict__ H, size_t n) {
    size_t i = ((size_t)blockIdx.x * blockDim.x + threadIdx.x) * 4;
    if (i >= n) return;
    float4 v = *(const float4*)(X + i);
    *(uint2*)(H + i) = make_uint2(pkb(__float2bfloat16(v.x), __float2bfloat16(v.y)),
                                  pkb(__float2bfloat16(v.z), __float2bfloat16(v.w)));
}

__global__ void transpose_hilo_kernel(const float* __restrict__ V,
                                      __nv_bfloat16* __restrict__ Th,
                                      __nv_bfloat16* __restrict__ Tl) {
    __shared__ float tile[32][33];
    int b = blockIdx.z, d0 = blockIdx.x * 32, j0 = blockIdx.y * 32;
    int tx = threadIdx.x, ty = threadIdx.y;
    #pragma unroll
    for (int r = 0; r < 32; r += 8)
        tile[ty + r][tx] = V[((size_t)b * S + j0 + ty + r) * D + d0 + tx];
    __syncthreads();
    #pragma unroll
    for (int r = 0; r < 32; r += 8) {
        float x = tile[tx][ty + r];
        __nv_bfloat16 h = __float2bfloat16(x);
        size_t o = ((size_t)b * D + d0 + ty + r) * S + j0 + tx;
        Th[o] = h;
        Tl[o] = __float2bfloat16(x - __bfloat162float(h));
    }
}

__global__ void reduce_rinv_kernel() {
    int idx = blockIdx.x * blockDim.x + threadIdx.x;
    if (idx >= NB * S) return;
    int b = idx / S, i = idx - b * S;
    float s = 0.f;
    #pragma unroll
    for (int t = 0; t < 16; ++t) s += g_rp[((size_t)(b * 16 + t)) * S + i];
    g_ri[idx] = 1.0f / fmaxf(s, 1e-12f);
}

__global__ void reduce_m2_kernel() {
    int idx = blockIdx.x * blockDim.x + threadIdx.x;
    if (idx >= NB * S) return;
    int b = idx / S, i = idx - b * S;
    float s = 0.f;
    #pragma unroll
    for (int t = 0; t < 4; ++t) s += g_mp[((size_t)(b * 4 + t)) * S + i];
    g_m2[idx] = s;
}

// ---------------- HMMA GEMM (1-product): C[128,128] = sum_k A[128,k]*B[128,k]^T ----------------
// BK=64, tile rows 64 bf16 (128B), SW128 swizzled. 3 stages x (A 16KB | B 16KB) = 96KB.
// EPI 0: Mh + m2 partials (sc=1)      EPI 1: weight epilogue (+Wl if WLO) + L1 partials
// EPI 2: Mh + m2 partials, sc=ri
template <int NDIM, int KDIM, int EPI, bool WLO>
__global__ void __launch_bounds__(256, 2)
tc_gemm(const __nv_bfloat16* __restrict__ Ah, const __nv_bfloat16* __restrict__ Bh,
        __nv_bfloat16* __restrict__ dstH, __nv_bfloat16* __restrict__ dstL,
        const float* __restrict__ Ain) {
    extern __shared__ char dsm[];
    const uint32_t sb = smem_u32(dsm);
    float* red = (float*)(dsm + 98304);   // [128][4]

    const int b = blockIdx.z;
    const int mBase = blockIdx.y * 128;
    const int nBase = blockIdx.x * 128;
    const int tid = threadIdx.x;
    const int lane = tid & 31, wid = tid >> 5;
    const int wm = wid & 1, wn = wid >> 1;

    const int grow_ld = tid >> 1;
    const int hsel = tid & 1;
    const __nv_bfloat16* pAh = Ah + (size_t)b * S * KDIM + (size_t)(mBase + grow_ld) * KDIM;
    const __nv_bfloat16* pBh = Bh + (size_t)b * NDIM * KDIM + (size_t)(nBase + grow_ld) * KDIM;

    const uint32_t rowb = (uint32_t)grow_ld * 128;
    const int nT = KDIM / 64;

    auto load_chunk = [&](int t, int stage) {
        if (t < nT) {
            const int kb = t * 64;
            const uint32_t ab = sb + stage * 16384;
            const uint32_t bb = sb + 49152 + stage * 16384;
            #pragma unroll
            for (int j = 0; j < 4; ++j) {
                const int seg = hsel * 4 + j;
                cpasync16(ab + SWZ(rowb + seg * 16), pAh + kb + seg * 8);
                cpasync16(bb + SWZ(rowb + seg * 16), pBh + kb + seg * 8);
            }
        }
        cp_commit();
    };

    float acc[4][4][4];
    #pragma unroll
    for (int i = 0; i < 4; ++i)
        #pragma unroll
        for (int j = 0; j < 4; ++j)
            #pragma unroll
            for (int e = 0; e < 4; ++e) acc[i][j][e] = 0.f;

    load_chunk(0, 0);
    load_chunk(1, 1);

    const int lrow = lane & 15, cseg = lane >> 4;

    int buf = 0, sld = 2;
    for (int t = 0; t < nT; ++t) {
        cp_wait<1>();
        __syncthreads();
        load_chunk(t + 2, sld);

        const uint32_t ab = sb + buf * 16384;
        const uint32_t bb = sb + 49152 + buf * 16384;

        #pragma unroll
        for (int s = 0; s < 4; ++s) {
            const uint32_t kcol = (uint32_t)(s * 2 + cseg) * 16;
            uint32_t bfh[2][4];
            #pragma unroll
            for (int g = 0; g < 2; ++g) {
                const uint32_t br = (uint32_t)(wn * 32 + g * 16 + lrow) * 128;
                ldsm4(bfh[g], bb + SWZ(br + kcol));
            }
            uint32_t afh[4][4];
            #pragma unroll
            for (int mf = 0; mf < 4; ++mf) {
                const uint32_t arr = (uint32_t)(wm * 64 + mf * 16 + lrow) * 128;
                ldsm4(afh[mf], ab + SWZ(arr + kcol));
            }
            #pragma unroll
            for (int mf = 0; mf < 4; ++mf)
                #pragma unroll
                for (int nf = 0; nf < 4; ++nf) {
                    const int g = nf >> 1, h = nf & 1;
                    mma_bf16(acc[mf][nf], afh[mf], bfh[g][h], bfh[g][h + 2]);
                }
        }
        buf = (buf == 2) ? 0 : buf + 1;
        sld = (sld == 2) ? 0 : sld + 1;
    }

    const int q = lane >> 2, tq = lane & 3;

    if (EPI == 1) {
        float v2c[4][2];
        #pragma unroll
        for (int nf = 0; nf < 4; ++nf) {
            float2 v2v = *(const float2*)(g_v2 + b * S + nBase + wn * 32 + nf * 8 + tq * 2);
            v2c[nf][0] = v2v.x; v2c[nf][1] = v2v.y;
        }
        #pragma unroll
        for (int mf = 0; mf < 4; ++mf) {
            #pragma unroll
            for (int r2 = 0; r2 < 2; ++r2) {
                const int lr = wm * 64 + mf * 16 + q + r2 * 8;
                const int gr = mBase + lr;
                const float m2v = g_m2[b * S + gr];
                const float* arow = Ain + ((size_t)b * S + gr) * S + nBase + wn * 32;
                __nv_bfloat16* whp = dstH + ((size_t)b * S + gr) * S + nBase + wn * 32;
                __nv_bfloat16* wlp = WLO ? dstL + ((size_t)b * S + gr) * S + nBase + wn * 32 : nullptr;
                float rs = 0.f;
                #pragma unroll
                for (int nf = 0; nf < 4; ++nf) {
                    float2 a2 = *(const float2*)(arow + nf * 8 + tq * 2);
                    float d2 = fmaxf(m2v + v2c[nf][0] - 2.f * acc[mf][nf][r2 * 2], 0.f);
                    float w0 = __fdividef(a2.x, sqrtf(d2) + EPSI);
                    d2 = fmaxf(m2v + v2c[nf][1] - 2.f * acc[mf][nf][r2 * 2 + 1], 0.f);
                    float w1 = __fdividef(a2.y, sqrtf(d2) + EPSI);
                    rs += fabsf(w0) + fabsf(w1);
                    __nv_bfloat16 h0 = __float2bfloat16(w0), h1 = __float2bfloat16(w1);
                    *(unsigned*)(whp + nf * 8 + tq * 2) = pkb(h0, h1);
                    if (WLO)
                        *(unsigned*)(wlp + nf * 8 + tq * 2) =
                            pkb(__float2bfloat16(w0 - __bfloat162float(h0)),
                                __float2bfloat16(w1 - __bfloat162float(h1)));
                }
                rs += __shfl_xor_sync(0xffffffffu, rs, 1);
                rs += __shfl_xor_sync(0xffffffffu, rs, 2);
                if (tq == 0) red[lr * 4 + wn] = rs;
            }
        }
        __syncthreads();
        if (tid < 128) {
            float s = red[tid * 4] + red[tid * 4 + 1] + red[tid * 4 + 2] + red[tid * 4 + 3];
            g_rp[((size_t)(b * 16 + blockIdx.x)) * S + mBase + tid] = s;
        }
    } else {
        // EPI 0 / 2: bf16 Mh store + m2 partials
        #pragma unroll
        for (int mf = 0; mf < 4; ++mf) {
            #pragma unroll
            for (int r2 = 0; r2 < 2; ++r2) {
                const int lr = wm * 64 + mf * 16 + q + r2 * 8;
                const int gr = mBase + lr;
                const float sc = (EPI == 2) ? g_ri[b * S + gr] : 1.f;
                __nv_bfloat16* hp = dstH + ((size_t)b * S + gr) * NDIM + nBase + wn * 32;
                float rs = 0.f;
                #pragma unroll
                for (int nf = 0; nf < 4; ++nf) {
                    float o0 = acc[mf][nf][r2 * 2] * sc;
                    float o1 = acc[mf][nf][r2 * 2 + 1] * sc;
                    rs += o0 * o0 + o1 * o1;
                    *(unsigned*)(hp + nf * 8 + tq * 2) =
                        pkb(__float2bfloat16(o0), __float2bfloat16(o1));
                }
                rs += __shfl_xor_sync(0xffffffffu, rs, 1);
                rs += __shfl_xor_sync(0xffffffffu, rs, 2);
                if (tq == 0) red[lr * 4 + wn] = rs;
            }
        }
        __syncthreads();
        if (tid < 128) {
            float s = red[tid * 4] + red[tid * 4 + 1] + red[tid * 4 + 2] + red[tid * 4 + 3];
            g_mp[((size_t)(b * 4 + blockIdx.x)) * S + mBase + tid] = s;
        }
    }
}

// ---------------- final GEMM: out = ri * (Wh@Vh + Wh@Vl + Wl@Vh), BK=64, occ1 ----------------
// 3 stages x 64KB (Ah | Al | Bh | Bl tiles, 16KB each) = 192KB.
__global__ void __launch_bounds__(256, 1)
tc_final(const __nv_bfloat16* __restrict__ Ah, const __nv_bfloat16* __restrict__ Al,
         const __nv_bfloat16* __restrict__ Bh, const __nv_bfloat16* __restrict__ Bl,
         float* __restrict__ dstF) {
    constexpr int NDIM = D, KDIM = S;
    extern __shared__ char dsm[];
    const uint32_t sb = smem_u32(dsm);

    const int b = blockIdx.z;
    const int mBase = blockIdx.y * 128;
    const int nBase = blockIdx.x * 128;
    const int tid = threadIdx.x;
    const int lane = tid & 31, wid = tid >> 5;
    const int wm = wid & 1, wn = wid >> 1;

    const int grow_ld = tid >> 1;
    const int hsel = tid & 1;
    const size_t aoff = (size_t)b * S * KDIM + (size_t)(mBase + grow_ld) * KDIM;
    const size_t boff = (size_t)b * NDIM * KDIM + (size_t)(nBase + grow_ld) * KDIM;
    const __nv_bfloat16* pAh = Ah + aoff;
    const __nv_bfloat16* pAl = Al + aoff;
    const __nv_bfloat16* pBh = Bh + boff;
    const __nv_bfloat16* pBl = Bl + boff;

    const uint32_t rowb = (uint32_t)grow_ld * 128;
    const int nT = KDIM / 64;   // 32

    auto load_chunk = [&](int t, int stage) {
        if (t < nT) {
            const int kb = t * 64;
            const uint32_t st = sb + stage * 65536;
            #pragma unroll
            for (int j = 0; j < 4; ++j) {
                const int seg = hsel * 4 + j;
                const uint32_t so = SWZ(rowb + seg * 16);
                cpasync16(st + so,         pAh + kb + seg * 8);
                cpasync16(st + 16384 + so, pAl + kb + seg * 8);
                cpasync16(st + 32768 + so, pBh + kb + seg * 8);
                cpasync16(st + 49152 + so, pBl + kb + seg * 8);
            }
        }
        cp_commit();
    };

    float acc[4][4][4];
    #pragma unroll
    for (int i = 0; i < 4; ++i)
        #pragma unroll
        for (int j = 0; j < 4; ++j)
            #pragma unroll
            for (int e = 0; e < 4; ++e) acc[i][j][e] = 0.f;

    load_chunk(0, 0);
    load_chunk(1, 1);

    const int lrow = lane & 15, cseg = lane >> 4;

    int buf = 0, sld = 2;
    for (int t = 0; t < nT; ++t) {
        cp_wait<1>();
        __syncthreads();
        load_chunk(t + 2, sld);

        const uint32_t st = sb + buf * 65536;

        #pragma unroll
        for (int s = 0; s < 4; ++s) {
            const uint32_t kcol = (uint32_t)(s * 2 + cseg) * 16;
            uint32_t bfh[2][4], bfl[2][4];
            #pragma unroll
            for (int g = 0; g < 2; ++g) {
                const uint32_t br = (uint32_t)(wn * 32 + g * 16 + lrow) * 128;
                ldsm4(bfh[g], st + 32768 + SWZ(br + kcol));
                ldsm4(bfl[g], st + 49152 + SWZ(br + kcol));
            }
            uint32_t afh[4][4], afl[4][4];
            #pragma unroll
            for (int mf = 0; mf < 4; ++mf) {
                const uint32_t arr = (uint32_t)(wm * 64 + mf * 16 + lrow) * 128;
                ldsm4(afh[mf], st + SWZ(arr + kcol));
                ldsm4(afl[mf], st + 16384 + SWZ(arr + kcol));
            }
            #pragma unroll
            for (int mf = 0; mf < 4; ++mf)
                #pragma unroll
                for (int nf = 0; nf < 4; ++nf) {
                    const int g = nf >> 1, h = nf & 1;
                    mma_bf16(acc[mf][nf], afh[mf], bfh[g][h], bfh[g][h + 2]);
                    mma_bf16(acc[mf][nf], afh[mf], bfl[g][h], bfl[g][h + 2]);
                    mma_bf16(acc[mf][nf], afl[mf], bfh[g][h], bfh[g][h + 2]);
                }
        }
        buf = (buf == 2) ? 0 : buf + 1;
        sld = (sld == 2) ? 0 : sld + 1;
    }

    const int q = lane >> 2, tq = lane & 3;
    #pragma unroll
    for (int mf = 0; mf < 4; ++mf) {
        #pragma unroll
        for (int r2 = 0; r2 < 2; ++r2) {
            const int gr = mBase + wm * 64 + mf * 16 + q + r2 * 8;
            const float sc = g_ri[b * S + gr];
            float* fo = dstF + ((size_t)b * S + gr) * NDIM + nBase + wn * 32;
            #pragma unroll
            for (int nf = 0; nf < 4; ++nf)
                *(float2*)(fo + nf * 8 + tq * 2) =
                    make_float2(acc[mf][nf][r2 * 2] * sc, acc[mf][nf][r2 * 2 + 1] * sc);
        }
    }
}

// ---------------- launch ----------------
extern "C" void kernel_launch(void* const* d_in, const int* in_sizes, int n_in,
                              void* d_out, int out_size) {
    const float* A = (const float*)d_in[0];
    const float* V = (const float*)d_in[1];
    float* out = (float*)d_out;

    void* p;
    cudaGetSymbolAddress(&p, g_Ah);  __nv_bfloat16* Ah = (__nv_bfloat16*)p;
    cudaGetSymbolAddress(&p, g_Wh);  __nv_bfloat16* Wh = (__nv_bfloat16*)p;
    cudaGetSymbolAddress(&p, g_Wl);  __nv_bfloat16* Wl = (__nv_bfloat16*)p;
    cudaGetSymbolAddress(&p, g_Mh);  __nv_bfloat16* Mh = (__nv_bfloat16*)p;
    cudaGetSymbolAddress(&p, g_Vh);  __nv_bfloat16* Vh = (__nv_bfloat16*)p;
    cudaGetSymbolAddress(&p, g_Vth); __nv_bfloat16* Vth = (__nv_bfloat16*)p;
    cudaGetSymbolAddress(&p, g_Vtl); __nv_bfloat16* Vtl = (__nv_bfloat16*)p;
    cudaGetSymbolAddress(&p, g_v2);  float* v2 = (float*)p;

    cudaFuncSetAttribute(tc_gemm<D, S, 0, false>, cudaFuncAttributeMaxDynamicSharedMemorySize, SMEMB);
    cudaFuncSetAttribute(tc_gemm<S, D, 1, false>, cudaFuncAttributeMaxDynamicSharedMemorySize, SMEMB);
    cudaFuncSetAttribute(tc_gemm<S, D, 1, true>,  cudaFuncAttributeMaxDynamicSharedMemorySize, SMEMB);
    cudaFuncSetAttribute(tc_gemm<D, S, 2, false>, cudaFuncAttributeMaxDynamicSharedMemorySize, SMEMB);
    cudaFuncSetAttribute(tc_final, cudaFuncAttributeMaxDynamicSharedMemorySize, SMEMB3);

    const int nrows = NB * S;
    const size_t nA = (size_t)NB * S * S;
    const size_t nV = (size_t)NB * S * D;

    convert_hi_kernel<<<(unsigned)((nA / 4 + 255) / 256), 256>>>(A, Ah, nA);
    convert_hi_kernel<<<(unsigned)((nV / 4 + 255) / 256), 256>>>(V, Vh, nV);
    transpose_hilo_kernel<<<dim3(D / 32, S / 32, NB), dim3(32, 8)>>>(V, Vth, Vtl);
    rownorm_kernel<<<(nrows * 32 + 255) / 256, 256>>>(V, v2, D, nrows);

    const dim3 gS(S / 128, S / 128, NB);
    const dim3 gD(D / 128, S / 128, NB);

    // M0 = A @ V -> Mh + m2 partials
    tc_gemm<D, S, 0, false><<<gD, 256, SMEMB>>>(Ah, Vth, Mh, nullptr, nullptr);
    reduce_m2_kernel<<<(NB * S + 255) / 256, 256>>>();

    for (int it = 0; it < 3; ++it) {
        const bool last = (it == 2);
        // W = A / (cdist(M,V)+eps); dot via Mh·Vh
        if (last)
            tc_gemm<S, D, 1, true><<<gS, 256, SMEMB>>>(Mh, Vh, Wh, Wl, A);
        else
            tc_gemm<S, D, 1, false><<<gS, 256, SMEMB>>>(Mh, Vh, Wh, nullptr, A);
        reduce_rinv_kernel<<<(NB * S + 255) / 256, 256>>>();

        if (last) {
            // out = ri * (Wh@Vh + Wh@Vl + Wl@Vh), fused 3-product, BK=64
            tc_final<<<gD, 256, SMEMB3>>>(Wh, Wl, Vth, Vtl, out);
        } else {
            // M = diag(1/l1) * (W @ V) -> Mh + m2 partials
            tc_gemm<D, S, 2, false><<<gD, 256, SMEMB>>>(Wh, Vth, Mh, nullptr, nullptr);
            reduce_m2_kernel<<<(NB * S + 255) / 256, 256>>>();
        }
    }
}

// round 13
// speedup vs baseline: 1.5234x; 1.0184x over previous
#include <cuda_runtime.h>
#include <cuda_bf16.h>
#include <cstdint>
#include <cstddef>

#define S 2048
#define D 512
#define NB 4
#define EPSI 0.01f
#define SWZ(x) ((x) ^ (((x) >> 3) & 0x70))
#define SMEMB (98304 + 2048 + 512)
#define SMEMB3 (196608 + 512)

// ---------------- device scratch ----------------
__device__ __align__(128) __nv_bfloat16  g_Ah [(size_t)NB * S * S];
__device__ __align__(128) __nv_bfloat16  g_Wh [(size_t)NB * S * S];
__device__ __align__(128) __nv_bfloat16  g_Wl [(size_t)NB * S * S];
__device__ __align__(128) __nv_bfloat16  g_Mh [(size_t)NB * S * D];
__device__ __align__(128) __nv_bfloat16  g_Vh [(size_t)NB * S * D];
__device__ __align__(128) __nv_bfloat16  g_Vth[(size_t)NB * D * S];
__device__ __align__(128) __nv_bfloat16  g_Vtl[(size_t)NB * D * S];
__device__ __align__(128) float          g_rp [(size_t)NB * 16 * S];
__device__ __align__(128) float          g_mp [(size_t)NB * 4 * S];
__device__ float g_v2[NB * S];

// ---------------- PTX helpers (compute_103-safe only) ----------------
__device__ __forceinline__ uint32_t smem_u32(const void* p) {
    uint32_t a;
    asm("{ .reg .u64 t; cvta.to.shared.u64 t, %1; cvt.u32.u64 %0, t; }" : "=r"(a) : "l"(p));
    return a;
}
__device__ __forceinline__ void cpasync16(uint32_t smem, const void* g) {
    asm volatile("cp.async.cg.shared.global [%0], [%1], 16;" :: "r"(smem), "l"(g));
}
__device__ __forceinline__ void cp_commit() {
    asm volatile("cp.async.commit_group;" ::: "memory");
}
template <int N>
__device__ __forceinline__ void cp_wait() {
    asm volatile("cp.async.wait_group %0;" :: "n"(N) : "memory");
}
__device__ __forceinline__ void ldsm4(uint32_t* r, uint32_t addr) {
    asm volatile("ldmatrix.sync.aligned.m8n8.x4.shared.b16 {%0,%1,%2,%3}, [%4];"
                 : "=r"(r[0]), "=r"(r[1]), "=r"(r[2]), "=r"(r[3]) : "r"(addr));
}
__device__ __forceinline__ void mma_bf16(float* c, const uint32_t* a, uint32_t b0, uint32_t b1) {
    asm volatile("mma.sync.aligned.m16n8k16.row.col.f32.bf16.bf16.f32 "
                 "{%0,%1,%2,%3}, {%4,%5,%6,%7}, {%8,%9}, {%0,%1,%2,%3};"
                 : "+f"(c[0]), "+f"(c[1]), "+f"(c[2]), "+f"(c[3])
                 : "r"(a[0]), "r"(a[1]), "r"(a[2]), "r"(a[3]), "r"(b0), "r"(b1));
}
__device__ __forceinline__ unsigned pkb(__nv_bfloat16 a, __nv_bfloat16 b) {
    unsigned short ua = *(unsigned short*)&a, ub = *(unsigned short*)&b;
    return (unsigned)ua | ((unsigned)ub << 16);
}

// ---------------- small kernels ----------------
__global__ void rownorm_kernel(const float* __restrict__ X, float* __restrict__ out,
                               int cols, int nrows) {
    int warp = (blockIdx.x * blockDim.x + threadIdx.x) >> 5;
    int lane = threadIdx.x & 31;
    if (warp >= nrows) return;
    const float* row = X + (size_t)warp * cols;
    float s = 0.f;
    for (int c = lane * 4; c < cols; c += 128) {
        float4 v = *(const float4*)(row + c);
        s += v.x * v.x + v.y * v.y + v.z * v.z + v.w * v.w;
    }
    #pragma unroll
    for (int off = 16; off >= 1; off >>= 1) s += __shfl_xor_sync(0xffffffffu, s, off);
    if (lane == 0) out[warp] = s;
}

__global__ void convert_hi_kernel(const float* __restrict__ X,
                                  __nv_bfloat16* __restrict__ H, size_t n) {
    size_t i = ((size_t)blockIdx.x * blockDim.x + threadIdx.x) * 4;
    if (i >= n) return;
    float4 v = *(const float4*)(X + i);
    *(uint2*)(H + i) = make_uint2(pkb(__float2bfloat16(v.x), __float2bfloat16(v.y)),
                                  pkb(__float2bfloat16(v.z), __float2bfloat16(v.w)));
}

__global__ void transpose_hilo_kernel(const float* __restrict__ V,
                                      __nv_bfloat16* __restrict__ Th,
                                      __nv_bfloat16* __restrict__ Tl) {
    __shared__ float tile[32][33];
    int b = blockIdx.z, d0 = blockIdx.x * 32, j0 = blockIdx.y * 32;
    int tx = threadIdx.x, ty = threadIdx.y;
    #pragma unroll
    for (int r = 0; r < 32; r += 8)
        tile[ty + r][tx] = V[((size_t)b * S + j0 + ty + r) * D + d0 + tx];
    __syncthreads();
    #pragma unroll
    for (int r = 0; r < 32; r += 8) {
        float x = tile[tx][ty + r];
        __nv_bfloat16 h = __float2bfloat16(x);
        size_t o = ((size_t)b * D + d0 + ty + r) * S + j0 + tx;
        Th[o] = h;
        Tl[o] = __float2bfloat16(x - __bfloat162float(h));
    }
}

// ---------------- HMMA GEMM (1-product): C[128,128] = sum_k A[128,k]*B[128,k]^T ----------------
// BK=64, tile rows 64 bf16 (128B), SW128 swizzled. 3 stages x (A 16KB | B 16KB) = 96KB.
// EPI 0: Mh + m2 partials (sc=1)
// EPI 1: weight epilogue (+Wl if WLO) + L1 partials; m2 reduced in fused prologue
// EPI 2: Mh + m2 partials, sc=ri; ri reduced in fused prologue
template <int NDIM, int KDIM, int EPI, bool WLO>
__global__ void __launch_bounds__(256, 2)
tc_gemm(const __nv_bfloat16* __restrict__ Ah, const __nv_bfloat16* __restrict__ Bh,
        __nv_bfloat16* __restrict__ dstH, __nv_bfloat16* __restrict__ dstL,
        const float* __restrict__ Ain) {
    extern __shared__ char dsm[];
    const uint32_t sb = smem_u32(dsm);
    float* red  = (float*)(dsm + 98304);          // [128][4]
    float* rowv = (float*)(dsm + 98304 + 2048);   // [128]

    const int b = blockIdx.z;
    const int mBase = blockIdx.y * 128;
    const int nBase = blockIdx.x * 128;
    const int tid = threadIdx.x;
    const int lane = tid & 31, wid = tid >> 5;
    const int wm = wid & 1, wn = wid >> 1;

    const int grow_ld = tid >> 1;
    const int hsel = tid & 1;
    const __nv_bfloat16* pAh = Ah + (size_t)b * S * KDIM + (size_t)(mBase + grow_ld) * KDIM;
    const __nv_bfloat16* pBh = Bh + (size_t)b * NDIM * KDIM + (size_t)(nBase + grow_ld) * KDIM;

    const uint32_t rowb = (uint32_t)grow_ld * 128;
    const int nT = KDIM / 64;

    auto load_chunk = [&](int t, int stage) {
        if (t < nT) {
            const int kb = t * 64;
            const uint32_t ab = sb + stage * 16384;
            const uint32_t bb = sb + 49152 + stage * 16384;
            #pragma unroll
            for (int j = 0; j < 4; ++j) {
                const int seg = hsel * 4 + j;
                cpasync16(ab + SWZ(rowb + seg * 16), pAh + kb + seg * 8);
                cpasync16(bb + SWZ(rowb + seg * 16), pBh + kb + seg * 8);
            }
        }
        cp_commit();
    };

    float acc[4][4][4];
    #pragma unroll
    for (int i = 0; i < 4; ++i)
        #pragma unroll
        for (int j = 0; j < 4; ++j)
            #pragma unroll
            for (int e = 0; e < 4; ++e) acc[i][j][e] = 0.f;

    load_chunk(0, 0);
    load_chunk(1, 1);

    // ---- fused row-stat prologue (overlaps stage-0/1 loads; mainloop barriers
    //      order the rowv write before the epilogue read) ----
    if (EPI == 1 && tid < 128) {
        float s = 0.f;
        #pragma unroll
        for (int t = 0; t < 4; ++t) s += g_mp[((size_t)(b * 4 + t)) * S + mBase + tid];
        rowv[tid] = s;
    }
    if (EPI == 2 && tid < 128) {
        float s = 0.f;
        #pragma unroll
        for (int t = 0; t < 16; ++t) s += g_rp[((size_t)(b * 16 + t)) * S + mBase + tid];
        rowv[tid] = 1.0f / fmaxf(s, 1e-12f);
    }

    const int lrow = lane & 15, cseg = lane >> 4;

    int buf = 0, sld = 2;
    for (int t = 0; t < nT; ++t) {
        cp_wait<1>();
        __syncthreads();
        load_chunk(t + 2, sld);

        const uint32_t ab = sb + buf * 16384;
        const uint32_t bb = sb + 49152 + buf * 16384;

        #pragma unroll
        for (int s = 0; s < 4; ++s) {
            const uint32_t kcol = (uint32_t)(s * 2 + cseg) * 16;
            uint32_t bfh[2][4];
            #pragma unroll
            for (int g = 0; g < 2; ++g) {
                const uint32_t br = (uint32_t)(wn * 32 + g * 16 + lrow) * 128;
                ldsm4(bfh[g], bb + SWZ(br + kcol));
            }
            uint32_t afh[4][4];
            #pragma unroll
            for (int mf = 0; mf < 4; ++mf) {
                const uint32_t arr = (uint32_t)(wm * 64 + mf * 16 + lrow) * 128;
                ldsm4(afh[mf], ab + SWZ(arr + kcol));
            }
            #pragma unroll
            for (int mf = 0; mf < 4; ++mf)
                #pragma unroll
                for (int nf = 0; nf < 4; ++nf) {
                    const int g = nf >> 1, h = nf & 1;
                    mma_bf16(acc[mf][nf], afh[mf], bfh[g][h], bfh[g][h + 2]);
                }
        }
        buf = (buf == 2) ? 0 : buf + 1;
        sld = (sld == 2) ? 0 : sld + 1;
    }

    const int q = lane >> 2, tq = lane & 3;

    if (EPI == 1) {
        float v2c[4][2];
        #pragma unroll
        for (int nf = 0; nf < 4; ++nf) {
            float2 v2v = *(const float2*)(g_v2 + b * S + nBase + wn * 32 + nf * 8 + tq * 2);
            v2c[nf][0] = v2v.x; v2c[nf][1] = v2v.y;
        }
        #pragma unroll
        for (int mf = 0; mf < 4; ++mf) {
            #pragma unroll
            for (int r2 = 0; r2 < 2; ++r2) {
                const int lr = wm * 64 + mf * 16 + q + r2 * 8;
                const int gr = mBase + lr;
                const float m2v = rowv[lr];
                const float* arow = Ain + ((size_t)b * S + gr) * S + nBase + wn * 32;
                __nv_bfloat16* whp = dstH + ((size_t)b * S + gr) * S + nBase + wn * 32;
                __nv_bfloat16* wlp = WLO ? dstL + ((size_t)b * S + gr) * S + nBase + wn * 32 : nullptr;
                float rs = 0.f;
                #pragma unroll
                for (int nf = 0; nf < 4; ++nf) {
                    float2 a2 = *(const float2*)(arow + nf * 8 + tq * 2);
                    float d2 = fmaxf(m2v + v2c[nf][0] - 2.f * acc[mf][nf][r2 * 2], 0.f);
                    float w0 = __fdividef(a2.x, sqrtf(d2) + EPSI);
                    d2 = fmaxf(m2v + v2c[nf][1] - 2.f * acc[mf][nf][r2 * 2 + 1], 0.f);
                    float w1 = __fdividef(a2.y, sqrtf(d2) + EPSI);
                    rs += fabsf(w0) + fabsf(w1);
                    __nv_bfloat16 h0 = __float2bfloat16(w0), h1 = __float2bfloat16(w1);
                    *(unsigned*)(whp + nf * 8 + tq * 2) = pkb(h0, h1);
                    if (WLO)
                        *(unsigned*)(wlp + nf * 8 + tq * 2) =
                            pkb(__float2bfloat16(w0 - __bfloat162float(h0)),
                                __float2bfloat16(w1 - __bfloat162float(h1)));
                }
                rs += __shfl_xor_sync(0xffffffffu, rs, 1);
                rs += __shfl_xor_sync(0xffffffffu, rs, 2);
                if (tq == 0) red[lr * 4 + wn] = rs;
            }
        }
        __syncthreads();
        if (tid < 128) {
            float s = red[tid * 4] + red[tid * 4 + 1] + red[tid * 4 + 2] + red[tid * 4 + 3];
            g_rp[((size_t)(b * 16 + blockIdx.x)) * S + mBase + tid] = s;
        }
    } else {
        // EPI 0 / 2: bf16 Mh store + m2 partials
        #pragma unroll
        for (int mf = 0; mf < 4; ++mf) {
            #pragma unroll
            for (int r2 = 0; r2 < 2; ++r2) {
                const int lr = wm * 64 + mf * 16 + q + r2 * 8;
                const int gr = mBase + lr;
                const float sc = (EPI == 2) ? rowv[lr] : 1.f;
                __nv_bfloat16* hp = dstH + ((size_t)b * S + gr) * NDIM + nBase + wn * 32;
                float rs = 0.f;
                #pragma unroll
                for (int nf = 0; nf < 4; ++nf) {
                    float o0 = acc[mf][nf][r2 * 2] * sc;
                    float o1 = acc[mf][nf][r2 * 2 + 1] * sc;
                    rs += o0 * o0 + o1 * o1;
                    *(unsigned*)(hp + nf * 8 + tq * 2) =
                        pkb(__float2bfloat16(o0), __float2bfloat16(o1));
                }
                rs += __shfl_xor_sync(0xffffffffu, rs, 1);
                rs += __shfl_xor_sync(0xffffffffu, rs, 2);
                if (tq == 0) red[lr * 4 + wn] = rs;
            }
        }
        __syncthreads();
        if (tid < 128) {
            float s = red[tid * 4] + red[tid * 4 + 1] + red[tid * 4 + 2] + red[tid * 4 + 3];
            g_mp[((size_t)(b * 4 + blockIdx.x)) * S + mBase + tid] = s;
        }
    }
}

// ---------------- final GEMM: out = ri * (Wh@Vh + Wh@Vl + Wl@Vh), BK=64, occ1 ----------------
// 3 stages x 64KB (Ah | Al | Bh | Bl tiles, 16KB each) = 192KB; rowv @192K.
__global__ void __launch_bounds__(256, 1)
tc_final(const __nv_bfloat16* __restrict__ Ah, const __nv_bfloat16* __restrict__ Al,
         const __nv_bfloat16* __restrict__ Bh, const __nv_bfloat16* __restrict__ Bl,
         float* __restrict__ dstF) {
    constexpr int NDIM = D, KDIM = S;
    extern __shared__ char dsm[];
    const uint32_t sb = smem_u32(dsm);
    float* rowv = (float*)(dsm + 196608);   // [128]

    const int b = blockIdx.z;
    const int mBase = blockIdx.y * 128;
    const int nBase = blockIdx.x * 128;
    const int tid = threadIdx.x;
    const int lane = tid & 31, wid = tid >> 5;
    const int wm = wid & 1, wn = wid >> 1;

    const int grow_ld = tid >> 1;
    const int hsel = tid & 1;
    const size_t aoff = (size_t)b * S * KDIM + (size_t)(mBase + grow_ld) * KDIM;
    const size_t boff = (size_t)b * NDIM * KDIM + (size_t)(nBase + grow_ld) * KDIM;
    const __nv_bfloat16* pAh = Ah + aoff;
    const __nv_bfloat16* pAl = Al + aoff;
    const __nv_bfloat16* pBh = Bh + boff;
    const __nv_bfloat16* pBl = Bl + boff;

    const uint32_t rowb = (uint32_t)grow_ld * 128;
    const int nT = KDIM / 64;   // 32

    auto load_chunk = [&](int t, int stage) {
        if (t < nT) {
            const int kb = t * 64;
            const uint32_t st = sb + stage * 65536;
            #pragma unroll
            for (int j = 0; j < 4; ++j) {
                const int seg = hsel * 4 + j;
                const uint32_t so = SWZ(rowb + seg * 16);
                cpasync16(st + so,         pAh + kb + seg * 8);
                cpasync16(st + 16384 + so, pAl + kb + seg * 8);
                cpasync16(st + 32768 + so, pBh + kb + seg * 8);
                cpasync16(st + 49152 + so, pBl + kb + seg * 8);
            }
        }
        cp_commit();
    };

    float acc[4][4][4];
    #pragma unroll
    for (int i = 0; i < 4; ++i)
        #pragma unroll
        for (int j = 0; j < 4; ++j)
            #pragma unroll
            for (int e = 0; e < 4; ++e) acc[i][j][e] = 0.f;

    load_chunk(0, 0);
    load_chunk(1, 1);

    // fused ri prologue
    if (tid < 128) {
        float s = 0.f;
        #pragma unroll
        for (int t = 0; t < 16; ++t) s += g_rp[((size_t)(b * 16 + t)) * S + mBase + tid];
        rowv[tid] = 1.0f / fmaxf(s, 1e-12f);
    }

    const int lrow = lane & 15, cseg = lane >> 4;

    int buf = 0, sld = 2;
    for (int t = 0; t < nT; ++t) {
        cp_wait<1>();
        __syncthreads();
        load_chunk(t + 2, sld);

        const uint32_t st = sb + buf * 65536;

        #pragma unroll
        for (int s = 0; s < 4; ++s) {
            const uint32_t kcol = (uint32_t)(s * 2 + cseg) * 16;
            uint32_t bfh[2][4], bfl[2][4];
            #pragma unroll
            for (int g = 0; g < 2; ++g) {
                const uint32_t br = (uint32_t)(wn * 32 + g * 16 + lrow) * 128;
                ldsm4(bfh[g], st + 32768 + SWZ(br + kcol));
                ldsm4(bfl[g], st + 49152 + SWZ(br + kcol));
            }
            uint32_t afh[4][4], afl[4][4];
            #pragma unroll
            for (int mf = 0; mf < 4; ++mf) {
                const uint32_t arr = (uint32_t)(wm * 64 + mf * 16 + lrow) * 128;
                ldsm4(afh[mf], st + SWZ(arr + kcol));
                ldsm4(afl[mf], st + 16384 + SWZ(arr + kcol));
            }
            #pragma unroll
            for (int mf = 0; mf < 4; ++mf)
                #pragma unroll
                for (int nf = 0; nf < 4; ++nf) {
                    const int g = nf >> 1, h = nf & 1;
                    mma_bf16(acc[mf][nf], afh[mf], bfh[g][h], bfh[g][h + 2]);
                    mma_bf16(acc[mf][nf], afh[mf], bfl[g][h], bfl[g][h + 2]);
                    mma_bf16(acc[mf][nf], afl[mf], bfh[g][h], bfh[g][h + 2]);
                }
        }
        buf = (buf == 2) ? 0 : buf + 1;
        sld = (sld == 2) ? 0 : sld + 1;
    }

    const int q = lane >> 2, tq = lane & 3;
    #pragma unroll
    for (int mf = 0; mf < 4; ++mf) {
        #pragma unroll
        for (int r2 = 0; r2 < 2; ++r2) {
            const int lr = wm * 64 + mf * 16 + q + r2 * 8;
            const int gr = mBase + lr;
            const float sc = rowv[lr];
            float* fo = dstF + ((size_t)b * S + gr) * NDIM + nBase + wn * 32;
            #pragma unroll
            for (int nf = 0; nf < 4; ++nf)
                *(float2*)(fo + nf * 8 + tq * 2) =
                    make_float2(acc[mf][nf][r2 * 2] * sc, acc[mf][nf][r2 * 2 + 1] * sc);
        }
    }
}

// ---------------- launch ----------------
extern "C" void kernel_launch(void* const* d_in, const int* in_sizes, int n_in,
                              void* d_out, int out_size) {
    const float* A = (const float*)d_in[0];
    const float* V = (const float*)d_in[1];
    float* out = (float*)d_out;

    void* p;
    cudaGetSymbolAddress(&p, g_Ah);  __nv_bfloat16* Ah = (__nv_bfloat16*)p;
    cudaGetSymbolAddress(&p, g_Wh);  __nv_bfloat16* Wh = (__nv_bfloat16*)p;
    cudaGetSymbolAddress(&p, g_Wl);  __nv_bfloat16* Wl = (__nv_bfloat16*)p;
    cudaGetSymbolAddress(&p, g_Mh);  __nv_bfloat16* Mh = (__nv_bfloat16*)p;
    cudaGetSymbolAddress(&p, g_Vh);  __nv_bfloat16* Vh = (__nv_bfloat16*)p;
    cudaGetSymbolAddress(&p, g_Vth); __nv_bfloat16* Vth = (__nv_bfloat16*)p;
    cudaGetSymbolAddress(&p, g_Vtl); __nv_bfloat16* Vtl = (__nv_bfloat16*)p;
    cudaGetSymbolAddress(&p, g_v2);  float* v2 = (float*)p;

    cudaFuncSetAttribute(tc_gemm<D, S, 0, false>, cudaFuncAttributeMaxDynamicSharedMemorySize, SMEMB);
    cudaFuncSetAttribute(tc_gemm<S, D, 1, false>, cudaFuncAttributeMaxDynamicSharedMemorySize, SMEMB);
    cudaFuncSetAttribute(tc_gemm<S, D, 1, true>,  cudaFuncAttributeMaxDynamicSharedMemorySize, SMEMB);
    cudaFuncSetAttribute(tc_gemm<D, S, 2, false>, cudaFuncAttributeMaxDynamicSharedMemorySize, SMEMB);
    cudaFuncSetAttribute(tc_final, cudaFuncAttributeMaxDynamicSharedMemorySize, SMEMB3);

    const int nrows = NB * S;
    const size_t nA = (size_t)NB * S * S;
    const size_t nV = (size_t)NB * S * D;

    convert_hi_kernel<<<(unsigned)((nA / 4 + 255) / 256), 256>>>(A, Ah, nA);
    convert_hi_kernel<<<(unsigned)((nV / 4 + 255) / 256), 256>>>(V, Vh, nV);
    transpose_hilo_kernel<<<dim3(D / 32, S / 32, NB), dim3(32, 8)>>>(V, Vth, Vtl);
    rownorm_kernel<<<(nrows * 32 + 255) / 256, 256>>>(V, v2, D, nrows);

    const dim3 gS(S / 128, S / 128, NB);
    const dim3 gD(D / 128, S / 128, NB);

    // M0 = A @ V -> Mh + m2 partials
    tc_gemm<D, S, 0, false><<<gD, 256, SMEMB>>>(Ah, Vth, Mh, nullptr, nullptr);

    for (int it = 0; it < 3; ++it) {
        const bool last = (it == 2);
        // W = A / (cdist(M,V)+eps); m2 reduced in prologue
        if (last)
            tc_gemm<S, D, 1, true><<<gS, 256, SMEMB>>>(Mh, Vh, Wh, Wl, A);
        else
            tc_gemm<S, D, 1, false><<<gS, 256, SMEMB>>>(Mh, Vh, Wh, nullptr, A);

        if (last) {
            // out = ri * (Wh@Vh + Wh@Vl + Wl@Vh); ri reduced in prologue
            tc_final<<<gD, 256, SMEMB3>>>(Wh, Wl, Vth, Vtl, out);
        } else {
            // M = diag(1/l1) * (W @ V); ri reduced in prologue -> Mh + m2 partials
            tc_gemm<D, S, 2, false><<<gD, 256, SMEMB>>>(Wh, Vth, Mh, nullptr, nullptr);
        }
    }
}

// round 14
// speedup vs baseline: 1.5283x; 1.0032x over previous
#include <cuda_runtime.h>
#include <cuda_bf16.h>
#include <cstdint>
#include <cstddef>

#define S 2048
#define D 512
#define NB 4
#define EPSI 0.01f
#define SWZ(x) ((x) ^ (((x) >> 3) & 0x70))
#define SMEMB (98304 + 2048 + 512)
#define SMEMBF (98304 + 512)

// ---------------- device scratch ----------------
__device__ __align__(128) __nv_bfloat16  g_Ah [(size_t)NB * S * S];
__device__ __align__(128) __nv_bfloat16  g_Wh [(size_t)NB * S * S];
__device__ __align__(128) __nv_bfloat16  g_Wl [(size_t)NB * S * S];
__device__ __align__(128) __nv_bfloat16  g_Mh [(size_t)NB * S * D];
__device__ __align__(128) __nv_bfloat16  g_Vh [(size_t)NB * S * D];
__device__ __align__(128) __nv_bfloat16  g_Vth[(size_t)NB * D * S];
__device__ __align__(128) __nv_bfloat16  g_Vtl[(size_t)NB * D * S];
__device__ __align__(128) float          g_rp [(size_t)NB * 16 * S];
__device__ __align__(128) float          g_mp [(size_t)NB * 4 * S];
__device__ float g_v2[NB * S];

// ---------------- PTX helpers (compute_103-safe only) ----------------
__device__ __forceinline__ uint32_t smem_u32(const void* p) {
    uint32_t a;
    asm("{ .reg .u64 t; cvta.to.shared.u64 t, %1; cvt.u32.u64 %0, t; }" : "=r"(a) : "l"(p));
    return a;
}
__device__ __forceinline__ void cpasync16(uint32_t smem, const void* g) {
    asm volatile("cp.async.cg.shared.global [%0], [%1], 16;" :: "r"(smem), "l"(g));
}
__device__ __forceinline__ void cp_commit() {
    asm volatile("cp.async.commit_group;" ::: "memory");
}
template <int N>
__device__ __forceinline__ void cp_wait() {
    asm volatile("cp.async.wait_group %0;" :: "n"(N) : "memory");
}
__device__ __forceinline__ void ldsm4(uint32_t* r, uint32_t addr) {
    asm volatile("ldmatrix.sync.aligned.m8n8.x4.shared.b16 {%0,%1,%2,%3}, [%4];"
                 : "=r"(r[0]), "=r"(r[1]), "=r"(r[2]), "=r"(r[3]) : "r"(addr));
}
__device__ __forceinline__ void mma_bf16(float* c, const uint32_t* a, uint32_t b0, uint32_t b1) {
    asm volatile("mma.sync.aligned.m16n8k16.row.col.f32.bf16.bf16.f32 "
                 "{%0,%1,%2,%3}, {%4,%5,%6,%7}, {%8,%9}, {%0,%1,%2,%3};"
                 : "+f"(c[0]), "+f"(c[1]), "+f"(c[2]), "+f"(c[3])
                 : "r"(a[0]), "r"(a[1]), "r"(a[2]), "r"(a[3]), "r"(b0), "r"(b1));
}
__device__ __forceinline__ unsigned pkb(__nv_bfloat16 a, __nv_bfloat16 b) {
    unsigned short ua = *(unsigned short*)&a, ub = *(unsigned short*)&b;
    return (unsigned)ua | ((unsigned)ub << 16);
}

// ---------------- small kernels ----------------
__global__ void rownorm_kernel(const float* __restrict__ X, float* __restrict__ out,
                               int cols, int nrows) {
    int warp = (blockIdx.x * blockDim.x + threadIdx.x) >> 5;
    int lane = threadIdx.x & 31;
    if (warp >= nrows) return;
    const float* row = X + (size_t)warp * cols;
    float s = 0.f;
    for (int c = lane * 4; c < cols; c += 128) {
        float4 v = *(const float4*)(row + c);
        s += v.x * v.x + v.y * v.y + v.z * v.z + v.w * v.w;
    }
    #pragma unroll
    for (int off = 16; off >= 1; off >>= 1) s += __shfl_xor_sync(0xffffffffu, s, off);
    if (lane == 0) out[warp] = s;
}

__global__ void convert_hi_kernel(const float* __restrict__ X,
                                  __nv_bfloat16* __restrict__ H, size_t n) {
    size_t i = ((size_t)blockIdx.x * blockDim.x + threadIdx.x) * 4;
    if (i >= n) return;
    float4 v = *(const float4*)(X + i);
    *(uint2*)(H + i) = make_uint2(pkb(__float2bfloat16(v.x), __float2bfloat16(v.y)),
                                  pkb(__float2bfloat16(v.z), __float2bfloat16(v.w)));
}

__global__ void transpose_hilo_kernel(const float* __restrict__ V,
                                      __nv_bfloat16* __restrict__ Th,
                                      __nv_bfloat16* __restrict__ Tl) {
    __shared__ float tile[32][33];
    int b = blockIdx.z, d0 = blockIdx.x * 32, j0 = blockIdx.y * 32;
    int tx = threadIdx.x, ty = threadIdx.y;
    #pragma unroll
    for (int r = 0; r < 32; r += 8)
        tile[ty + r][tx] = V[((size_t)b * S + j0 + ty + r) * D + d0 + tx];
    __syncthreads();
    #pragma unroll
    for (int r = 0; r < 32; r += 8) {
        float x = tile[tx][ty + r];
        __nv_bfloat16 h = __float2bfloat16(x);
        size_t o = ((size_t)b * D + d0 + ty + r) * S + j0 + tx;
        Th[o] = h;
        Tl[o] = __float2bfloat16(x - __bfloat162float(h));
    }
}

// ---------------- HMMA GEMM (1-product): C[128,128] = sum_k A[128,k]*B[128,k]^T ----------------
// BK=64, tile rows 64 bf16 (128B), SW128 swizzled. 3 stages x (A 16KB | B 16KB) = 96KB.
// EPI 0: Mh + m2 partials (sc=1)
// EPI 1: weight epilogue (+Wl if WLO) + L1 partials; m2 reduced in fused prologue
// EPI 2: Mh + m2 partials, sc=ri; ri reduced in fused prologue
template <int NDIM, int KDIM, int EPI, bool WLO>
__global__ void __launch_bounds__(256, 2)
tc_gemm(const __nv_bfloat16* __restrict__ Ah, const __nv_bfloat16* __restrict__ Bh,
        __nv_bfloat16* __restrict__ dstH, __nv_bfloat16* __restrict__ dstL,
        const float* __restrict__ Ain) {
    extern __shared__ char dsm[];
    const uint32_t sb = smem_u32(dsm);
    float* red  = (float*)(dsm + 98304);          // [128][4]
    float* rowv = (float*)(dsm + 98304 + 2048);   // [128]

    const int b = blockIdx.z;
    const int mBase = blockIdx.y * 128;
    const int nBase = blockIdx.x * 128;
    const int tid = threadIdx.x;
    const int lane = tid & 31, wid = tid >> 5;
    const int wm = wid & 1, wn = wid >> 1;

    const int grow_ld = tid >> 1;
    const int hsel = tid & 1;
    const __nv_bfloat16* pAh = Ah + (size_t)b * S * KDIM + (size_t)(mBase + grow_ld) * KDIM;
    const __nv_bfloat16* pBh = Bh + (size_t)b * NDIM * KDIM + (size_t)(nBase + grow_ld) * KDIM;

    const uint32_t rowb = (uint32_t)grow_ld * 128;
    const int nT = KDIM / 64;

    auto load_chunk = [&](int t, int stage) {
        if (t < nT) {
            const int kb = t * 64;
            const uint32_t ab = sb + stage * 16384;
            const uint32_t bb = sb + 49152 + stage * 16384;
            #pragma unroll
            for (int j = 0; j < 4; ++j) {
                const int seg = hsel * 4 + j;
                cpasync16(ab + SWZ(rowb + seg * 16), pAh + kb + seg * 8);
                cpasync16(bb + SWZ(rowb + seg * 16), pBh + kb + seg * 8);
            }
        }
        cp_commit();
    };

    float acc[4][4][4];
    #pragma unroll
    for (int i = 0; i < 4; ++i)
        #pragma unroll
        for (int j = 0; j < 4; ++j)
            #pragma unroll
            for (int e = 0; e < 4; ++e) acc[i][j][e] = 0.f;

    load_chunk(0, 0);
    load_chunk(1, 1);

    // ---- fused row-stat prologue (overlaps stage-0/1 loads) ----
    if (EPI == 1 && tid < 128) {
        float s = 0.f;
        #pragma unroll
        for (int t = 0; t < 4; ++t) s += g_mp[((size_t)(b * 4 + t)) * S + mBase + tid];
        rowv[tid] = s;
    }
    if (EPI == 2 && tid < 128) {
        float s = 0.f;
        #pragma unroll
        for (int t = 0; t < 16; ++t) s += g_rp[((size_t)(b * 16 + t)) * S + mBase + tid];
        rowv[tid] = 1.0f / fmaxf(s, 1e-12f);
    }

    const int lrow = lane & 15, cseg = lane >> 4;

    int buf = 0, sld = 2;
    for (int t = 0; t < nT; ++t) {
        cp_wait<1>();
        __syncthreads();
        load_chunk(t + 2, sld);

        const uint32_t ab = sb + buf * 16384;
        const uint32_t bb = sb + 49152 + buf * 16384;

        #pragma unroll
        for (int s = 0; s < 4; ++s) {
            const uint32_t kcol = (uint32_t)(s * 2 + cseg) * 16;
            uint32_t bfh[2][4];
            #pragma unroll
            for (int g = 0; g < 2; ++g) {
                const uint32_t br = (uint32_t)(wn * 32 + g * 16 + lrow) * 128;
                ldsm4(bfh[g], bb + SWZ(br + kcol));
            }
            uint32_t afh[4][4];
            #pragma unroll
            for (int mf = 0; mf < 4; ++mf) {
                const uint32_t arr = (uint32_t)(wm * 64 + mf * 16 + lrow) * 128;
                ldsm4(afh[mf], ab + SWZ(arr + kcol));
            }
            #pragma unroll
            for (int mf = 0; mf < 4; ++mf)
                #pragma unroll
                for (int nf = 0; nf < 4; ++nf) {
                    const int g = nf >> 1, h = nf & 1;
                    mma_bf16(acc[mf][nf], afh[mf], bfh[g][h], bfh[g][h + 2]);
                }
        }
        buf = (buf == 2) ? 0 : buf + 1;
        sld = (sld == 2) ? 0 : sld + 1;
    }

    const int q = lane >> 2, tq = lane & 3;

    if (EPI == 1) {
        float v2c[4][2];
        #pragma unroll
        for (int nf = 0; nf < 4; ++nf) {
            float2 v2v = *(const float2*)(g_v2 + b * S + nBase + wn * 32 + nf * 8 + tq * 2);
            v2c[nf][0] = v2v.x; v2c[nf][1] = v2v.y;
        }
        #pragma unroll
        for (int mf = 0; mf < 4; ++mf) {
            #pragma unroll
            for (int r2 = 0; r2 < 2; ++r2) {
                const int lr = wm * 64 + mf * 16 + q + r2 * 8;
                const int gr = mBase + lr;
                const float m2v = rowv[lr];
                const float* arow = Ain + ((size_t)b * S + gr) * S + nBase + wn * 32;
                __nv_bfloat16* whp = dstH + ((size_t)b * S + gr) * S + nBase + wn * 32;
                __nv_bfloat16* wlp = WLO ? dstL + ((size_t)b * S + gr) * S + nBase + wn * 32 : nullptr;
                float rs = 0.f;
                #pragma unroll
                for (int nf = 0; nf < 4; ++nf) {
                    float2 a2 = *(const float2*)(arow + nf * 8 + tq * 2);
                    float d2 = fmaxf(m2v + v2c[nf][0] - 2.f * acc[mf][nf][r2 * 2], 0.f);
                    float w0 = __fdividef(a2.x, sqrtf(d2) + EPSI);
                    d2 = fmaxf(m2v + v2c[nf][1] - 2.f * acc[mf][nf][r2 * 2 + 1], 0.f);
                    float w1 = __fdividef(a2.y, sqrtf(d2) + EPSI);
                    rs += fabsf(w0) + fabsf(w1);
                    __nv_bfloat16 h0 = __float2bfloat16(w0), h1 = __float2bfloat16(w1);
                    *(unsigned*)(whp + nf * 8 + tq * 2) = pkb(h0, h1);
                    if (WLO)
                        *(unsigned*)(wlp + nf * 8 + tq * 2) =
                            pkb(__float2bfloat16(w0 - __bfloat162float(h0)),
                                __float2bfloat16(w1 - __bfloat162float(h1)));
                }
                rs += __shfl_xor_sync(0xffffffffu, rs, 1);
                rs += __shfl_xor_sync(0xffffffffu, rs, 2);
                if (tq == 0) red[lr * 4 + wn] = rs;
            }
        }
        __syncthreads();
        if (tid < 128) {
            float s = red[tid * 4] + red[tid * 4 + 1] + red[tid * 4 + 2] + red[tid * 4 + 3];
            g_rp[((size_t)(b * 16 + blockIdx.x)) * S + mBase + tid] = s;
        }
    } else {
        // EPI 0 / 2: bf16 Mh store + m2 partials
        #pragma unroll
        for (int mf = 0; mf < 4; ++mf) {
            #pragma unroll
            for (int r2 = 0; r2 < 2; ++r2) {
                const int lr = wm * 64 + mf * 16 + q + r2 * 8;
                const int gr = mBase + lr;
                const float sc = (EPI == 2) ? rowv[lr] : 1.f;
                __nv_bfloat16* hp = dstH + ((size_t)b * S + gr) * NDIM + nBase + wn * 32;
                float rs = 0.f;
                #pragma unroll
                for (int nf = 0; nf < 4; ++nf) {
                    float o0 = acc[mf][nf][r2 * 2] * sc;
                    float o1 = acc[mf][nf][r2 * 2 + 1] * sc;
                    rs += o0 * o0 + o1 * o1;
                    *(unsigned*)(hp + nf * 8 + tq * 2) =
                        pkb(__float2bfloat16(o0), __float2bfloat16(o1));
                }
                rs += __shfl_xor_sync(0xffffffffu, rs, 1);
                rs += __shfl_xor_sync(0xffffffffu, rs, 2);
                if (tq == 0) red[lr * 4 + wn] = rs;
            }
        }
        __syncthreads();
        if (tid < 128) {
            float s = red[tid * 4] + red[tid * 4 + 1] + red[tid * 4 + 2] + red[tid * 4 + 3];
            g_mp[((size_t)(b * 4 + blockIdx.x)) * S + mBase + tid] = s;
        }
    }
}

// ---------------- final GEMM (occ2): out = ri * (Wh@Vh + Wh@Vl + Wl@Vh) ----------------
// BK=32, rows [hi 32 bf16 | lo 32 bf16] (128B). 3 stages x (A 16KB | B 16KB) = 96KB.
// A fragments loaded per-mf to keep register liveness < 128 (occ2).
__global__ void __launch_bounds__(256, 2)
tc_final(const __nv_bfloat16* __restrict__ Ah, const __nv_bfloat16* __restrict__ Al,
         const __nv_bfloat16* __restrict__ Bh, const __nv_bfloat16* __restrict__ Bl,
         float* __restrict__ dstF) {
    constexpr int NDIM = D, KDIM = S;
    extern __shared__ char dsm[];
    const uint32_t sb = smem_u32(dsm);
    float* rowv = (float*)(dsm + 98304);   // [128]

    const int b = blockIdx.z;
    const int mBase = blockIdx.y * 128;
    const int nBase = blockIdx.x * 128;
    const int tid = threadIdx.x;
    const int lane = tid & 31, wid = tid >> 5;
    const int wm = wid & 1, wn = wid >> 1;

    const int grow_ld = tid >> 1;
    const int hsel = tid & 1;
    const size_t aoff = (size_t)b * S * KDIM + (size_t)(mBase + grow_ld) * KDIM;
    const size_t boff = (size_t)b * NDIM * KDIM + (size_t)(nBase + grow_ld) * KDIM;
    const __nv_bfloat16* pAh = Ah + aoff;
    const __nv_bfloat16* pAl = Al + aoff;
    const __nv_bfloat16* pBh = Bh + boff;
    const __nv_bfloat16* pBl = Bl + boff;

    const uint32_t rowb = (uint32_t)grow_ld * 128;
    const int nT = KDIM / 32;   // 64 chunks

    auto load_chunk = [&](int t, int stage) {
        if (t < nT) {
            const int kb = t * 32;
            const uint32_t ab = sb + stage * 16384;
            const uint32_t bb = sb + 49152 + stage * 16384;
            #pragma unroll
            for (int j = 0; j < 2; ++j) {
                const int seg = hsel * 2 + j;
                cpasync16(ab + SWZ(rowb + seg * 16),      pAh + kb + seg * 8);
                cpasync16(ab + SWZ(rowb + 64 + seg * 16), pAl + kb + seg * 8);
                cpasync16(bb + SWZ(rowb + seg * 16),      pBh + kb + seg * 8);
                cpasync16(bb + SWZ(rowb + 64 + seg * 16), pBl + kb + seg * 8);
            }
        }
        cp_commit();
    };

    float acc[4][4][4];
    #pragma unroll
    for (int i = 0; i < 4; ++i)
        #pragma unroll
        for (int j = 0; j < 4; ++j)
            #pragma unroll
            for (int e = 0; e < 4; ++e) acc[i][j][e] = 0.f;

    load_chunk(0, 0);
    load_chunk(1, 1);

    // fused ri prologue
    if (tid < 128) {
        float s = 0.f;
        #pragma unroll
        for (int t = 0; t < 16; ++t) s += g_rp[((size_t)(b * 16 + t)) * S + mBase + tid];
        rowv[tid] = 1.0f / fmaxf(s, 1e-12f);
    }

    const int lrow = lane & 15, cseg = lane >> 4;

    int buf = 0, sld = 2;
    for (int t = 0; t < nT; ++t) {
        cp_wait<1>();
        __syncthreads();
        load_chunk(t + 2, sld);

        const uint32_t ab = sb + buf * 16384;
        const uint32_t bb = sb + 49152 + buf * 16384;

        #pragma unroll
        for (int s = 0; s < 2; ++s) {
            const uint32_t kcol = (uint32_t)(s * 2 + cseg) * 16;
            uint32_t bfh[2][4], bfl[2][4];
            #pragma unroll
            for (int g = 0; g < 2; ++g) {
                const uint32_t br = (uint32_t)(wn * 32 + g * 16 + lrow) * 128;
                ldsm4(bfh[g], bb + SWZ(br + kcol));
                ldsm4(bfl[g], bb + SWZ(br + 64 + kcol));
            }
            // per-mf A loads: only one mf's hi/lo fragments live at a time
            #pragma unroll
            for (int mf = 0; mf < 4; ++mf) {
                uint32_t afh[4], afl[4];
                const uint32_t arr = (uint32_t)(wm * 64 + mf * 16 + lrow) * 128;
                ldsm4(afh, ab + SWZ(arr + kcol));
                ldsm4(afl, ab + SWZ(arr + 64 + kcol));
                #pragma unroll
                for (int nf = 0; nf < 4; ++nf) {
                    const int g = nf >> 1, h = nf & 1;
                    mma_bf16(acc[mf][nf], afh, bfh[g][h], bfh[g][h + 2]);
                    mma_bf16(acc[mf][nf], afh, bfl[g][h], bfl[g][h + 2]);
                    mma_bf16(acc[mf][nf], afl, bfh[g][h], bfh[g][h + 2]);
                }
            }
        }
        buf = (buf == 2) ? 0 : buf + 1;
        sld = (sld == 2) ? 0 : sld + 1;
    }

    const int q = lane >> 2, tq = lane & 3;
    #pragma unroll
    for (int mf = 0; mf < 4; ++mf) {
        #pragma unroll
        for (int r2 = 0; r2 < 2; ++r2) {
            const int lr = wm * 64 + mf * 16 + q + r2 * 8;
            const int gr = mBase + lr;
            const float sc = rowv[lr];
            float* fo = dstF + ((size_t)b * S + gr) * NDIM + nBase + wn * 32;
            #pragma unroll
            for (int nf = 0; nf < 4; ++nf)
                *(float2*)(fo + nf * 8 + tq * 2) =
                    make_float2(acc[mf][nf][r2 * 2] * sc, acc[mf][nf][r2 * 2 + 1] * sc);
        }
    }
}

// ---------------- launch ----------------
extern "C" void kernel_launch(void* const* d_in, const int* in_sizes, int n_in,
                              void* d_out, int out_size) {
    const float* A = (const float*)d_in[0];
    const float* V = (const float*)d_in[1];
    float* out = (float*)d_out;

    void* p;
    cudaGetSymbolAddress(&p, g_Ah);  __nv_bfloat16* Ah = (__nv_bfloat16*)p;
    cudaGetSymbolAddress(&p, g_Wh);  __nv_bfloat16* Wh = (__nv_bfloat16*)p;
    cudaGetSymbolAddress(&p, g_Wl);  __nv_bfloat16* Wl = (__nv_bfloat16*)p;
    cudaGetSymbolAddress(&p, g_Mh);  __nv_bfloat16* Mh = (__nv_bfloat16*)p;
    cudaGetSymbolAddress(&p, g_Vh);  __nv_bfloat16* Vh = (__nv_bfloat16*)p;
    cudaGetSymbolAddress(&p, g_Vth); __nv_bfloat16* Vth = (__nv_bfloat16*)p;
    cudaGetSymbolAddress(&p, g_Vtl); __nv_bfloat16* Vtl = (__nv_bfloat16*)p;
    cudaGetSymbolAddress(&p, g_v2);  float* v2 = (float*)p;

    cudaFuncSetAttribute(tc_gemm<D, S, 0, false>, cudaFuncAttributeMaxDynamicSharedMemorySize, SMEMB);
    cudaFuncSetAttribute(tc_gemm<S, D, 1, false>, cudaFuncAttributeMaxDynamicSharedMemorySize, SMEMB);
    cudaFuncSetAttribute(tc_gemm<S, D, 1, true>,  cudaFuncAttributeMaxDynamicSharedMemorySize, SMEMB);
    cudaFuncSetAttribute(tc_gemm<D, S, 2, false>, cudaFuncAttributeMaxDynamicSharedMemorySize, SMEMB);
    cudaFuncSetAttribute(tc_final, cudaFuncAttributeMaxDynamicSharedMemorySize, SMEMBF);

    const int nrows = NB * S;
    const size_t nA = (size_t)NB * S * S;
    const size_t nV = (size_t)NB * S * D;

    convert_hi_kernel<<<(unsigned)((nA / 4 + 255) / 256), 256>>>(A, Ah, nA);
    convert_hi_kernel<<<(unsigned)((nV / 4 + 255) / 256), 256>>>(V, Vh, nV);
    transpose_hilo_kernel<<<dim3(D / 32, S / 32, NB), dim3(32, 8)>>>(V, Vth, Vtl);
    rownorm_kernel<<<(nrows * 32 + 255) / 256, 256>>>(V, v2, D, nrows);

    const dim3 gS(S / 128, S / 128, NB);
    const dim3 gD(D / 128, S / 128, NB);

    // M0 = A @ V -> Mh + m2 partials
    tc_gemm<D, S, 0, false><<<gD, 256, SMEMB>>>(Ah, Vth, Mh, nullptr, nullptr);

    for (int it = 0; it < 3; ++it) {
        const bool last = (it == 2);
        // W = A / (cdist(M,V)+eps); m2 reduced in prologue
        if (last)
            tc_gemm<S, D, 1, true><<<gS, 256, SMEMB>>>(Mh, Vh, Wh, Wl, A);
        else
            tc_gemm<S, D, 1, false><<<gS, 256, SMEMB>>>(Mh, Vh, Wh, nullptr, A);

        if (last) {
            // out = ri * (Wh@Vh + Wh@Vl + Wl@Vh); occ2, ri reduced in prologue
            tc_final<<<gD, 256, SMEMBF>>>(Wh, Wl, Vth, Vtl, out);
        } else {
            // M = diag(1/l1) * (W @ V); ri reduced in prologue -> Mh + m2 partials
            tc_gemm<D, S, 2, false><<<gD, 256, SMEMB>>>(Wh, Vth, Mh, nullptr, nullptr);
        }
    }
}